// round 14
// baseline (speedup 1.0000x reference)
#include <cuda_runtime.h>
#include <cuda_bf16.h>
#include <math.h>
#include <stdint.h>

// ---------------- problem constants ----------------
#define BB 4
#define HI 56
#define WI 56
#define DD 256
#define HO 28
#define WO 28
#define NPOS 784
#define NTOK (BB*NPOS)     // 3136
#define NTOKP 3200
#define NTOKIN (BB*HI*WI)  // 12544
#define HEADS 8
#define LN_EPS 1e-5f

typedef __nv_bfloat16 bf16;

// ---------------- scratch (device globals) ----------------
__device__ float g_xout  [NTOK*DD];
__device__ float g_buf2  [NTOK*768];
__device__ float g_kg    [BB*4*NPOS*DD];
__device__ float g_vg    [BB*4*NPOS*DD];
__device__ float g_split [3*NTOKP*DD];
__device__ float g_attn  [BB*4*NPOS*9];
__device__ float g_colsum[BB*NPOS];
__device__ float g_cos   [NPOS*16];
__device__ float g_sin   [NPOS*16];

__device__ bf16 g_xh[NTOKIN*DD],  g_xl[NTOKIN*DD];
__device__ bf16 g_lnxh[NTOKIN*DD],g_lnxl[NTOKIN*DD];
__device__ bf16 g_colh[NTOKP*2304], g_coll[NTOKP*2304];
__device__ bf16 g_a1h[NTOKP*768], g_a1l[NTOKP*768];
__device__ bf16 g_a2h[NTOKP*256], g_a2l[NTOKP*256];
__device__ bf16 g_wsh[DD*2304], g_wsl[DD*2304];
__device__ bf16 g_wqh[DD*DD],   g_wql[DD*DD];
__device__ bf16 g_wkh[DD*DD],   g_wkl[DD*DD];
__device__ bf16 g_wvh[DD*DD],   g_wvl[DD*DD];
__device__ bf16 g_m1h[512*DD],  g_m1l[512*DD];
__device__ bf16 g_m2h[DD*512],  g_m2l[DD*512];
__device__ bf16 g_qkvh[2*768*DD], g_qkvl[2*768*DD];
__device__ bf16 g_pjh[2*DD*DD],   g_pjl[2*DD*DD];
__device__ bf16 g_bm1h[2*768*DD], g_bm1l[2*768*DD];
__device__ bf16 g_bm2h[2*DD*768], g_bm2l[2*DD*768];

// ---------------- helpers ----------------
__device__ __forceinline__ uint32_t smem_u32(const void* p) {
    uint32_t a;
    asm("{ .reg .u64 t; cvta.to.shared.u64 t, %1; cvt.u32.u64 %0, t; }" : "=r"(a) : "l"(p));
    return a;
}
__device__ __forceinline__ float gelu_exact(float x) {
    return 0.5f * x * (1.f + erff(x * 0.70710678118654752f));
}
__device__ __forceinline__ void cp16(uint32_t saddr, const void* gaddr) {
    asm volatile("cp.async.cg.shared.global [%0], [%1], 16;" :: "r"(saddr), "l"(gaddr));
}
#define CP_COMMIT() asm volatile("cp.async.commit_group;" ::: "memory")
#define CP_WAIT0()  asm volatile("cp.async.wait_group 0;" ::: "memory")

__device__ __forceinline__ void ldmx4(uint32_t addr, uint32_t* r) {
    asm volatile("ldmatrix.sync.aligned.m8n8.x4.shared.b16 {%0,%1,%2,%3}, [%4];"
        : "=r"(r[0]), "=r"(r[1]), "=r"(r[2]), "=r"(r[3]) : "r"(addr));
}
__device__ __forceinline__ void mma16816(float* d, const uint32_t* a, uint32_t b0, uint32_t b1) {
    asm volatile("mma.sync.aligned.m16n8k16.row.col.f32.bf16.bf16.f32 "
        "{%0,%1,%2,%3}, {%4,%5,%6,%7}, {%8,%9}, {%0,%1,%2,%3};"
        : "+f"(d[0]), "+f"(d[1]), "+f"(d[2]), "+f"(d[3])
        : "r"(a[0]), "r"(a[1]), "r"(a[2]), "r"(a[3]), "r"(b0), "r"(b1));
}
__device__ __forceinline__ void split_hl(float v, bf16& h, bf16& l) {
    h = __float2bfloat16(v);
    l = __float2bfloat16(v - __bfloat162float(h));
}

// ---------------- tensor-core GEMM (mma.sync bf16 hi/lo 3-pass) ----------------
// Tile M=64, N=64, K-chunk 64; all tiles 64x144B.
// BUFSZ = 4*9216 = 36864; double-buffered 73728 => 3 CTAs/SM.
// Register-level software pipeline: kk+1 fragments issued before kk's MMAs.
#define TROW 144
#define ATSZ (64*TROW)          // 9216
#define BUFSZ (4*ATSZ)          // 36864
#define GTC_SMEM (2*BUFSZ)      // 73728

__global__ void __launch_bounds__(256, 3)
gemm_mma(const bf16* __restrict__ Ah, const bf16* __restrict__ Al,
         const bf16* __restrict__ Bh, const bf16* __restrict__ Bl,
         const float* __restrict__ bias, float* __restrict__ C,
         bf16* __restrict__ Oh, bf16* __restrict__ Ol,
         const float* __restrict__ CS, const float* __restrict__ SN,
         int Mreal, int Mpad, int N, int K, int act, int remap, int ksplit) {
    extern __shared__ char smraw[];
    uint32_t sb = smem_u32(smraw);
    int tid = threadIdx.x, wid = tid >> 5, lane = tid & 31;
    int wm = wid >> 2, wn = wid & 3;          // 2 x 4 warps, warp tile 32x16
    int bm = blockIdx.y * 64, bn = blockIdx.x * 64;
    int kper = K / ksplit;
    int kbase = blockIdx.z * kper;
    int nch = kper / 64;

    const bf16* srcA[2] = { Ah + (size_t)bm*K, Al + (size_t)bm*K };
    const bf16* srcB[2] = { Bh + (size_t)bn*K, Bl + (size_t)bn*K };

    #define LOAD_CHUNK(c, b) {                                                  \
        int k0 = kbase + (c)*64;                                                \
        uint32_t dbase = sb + (b)*BUFSZ;                                        \
        _Pragma("unroll")                                                       \
        for (int s = 0; s < 2; s++) {                                           \
            _Pragma("unroll")                                                   \
            for (int u = 0; u < 2; u++) {                                       \
                int idx = tid + u*256;                                          \
                int row = idx >> 3, seg = idx & 7;                              \
                cp16(dbase + s*ATSZ + row*TROW + seg*16,                        \
                     srcA[s] + (size_t)row*K + k0 + seg*8);                     \
            }                                                                   \
        }                                                                       \
        _Pragma("unroll")                                                       \
        for (int s = 0; s < 2; s++) {                                           \
            uint32_t dst = dbase + 2*ATSZ + s*ATSZ;                             \
            _Pragma("unroll")                                                   \
            for (int u = 0; u < 2; u++) {                                       \
                int idx = tid + u*256;                                          \
                int brow = idx >> 3, bseg = idx & 7;                            \
                cp16(dst + brow*TROW + bseg*16,                                 \
                     srcB[s] + (size_t)brow*K + k0 + bseg*8);                   \
            }                                                                   \
        }                                                                       \
        CP_COMMIT();                                                            \
    }

    float acc[2][2][4];
    #pragma unroll
    for (int i=0;i<2;i++)
        #pragma unroll
        for (int j=0;j<2;j++)
            #pragma unroll
            for (int e=0;e<4;e++) acc[i][j][e] = 0.f;

    LOAD_CHUNK(0, 0)
    int buf = 0;
    int lr16 = lane & 15, lh = lane >> 4;
    int arow0 = wm*32 + lr16, arow1 = wm*32 + 16 + lr16;
    int brow  = wn*16 + lr16;

    // fragment double buffers
    uint32_t ah[2][2][4], al[2][2][4], bh[2][4], bl[2][4];

    #define LOAD_FRAGS(kk, fb, aHp, aLp, bHp, bLp) {                            \
        int kb = (kk)*32 + lh*16;                                               \
        ldmx4((aHp) + arow0*TROW + kb, ah[fb][0]);                              \
        ldmx4((aHp) + arow1*TROW + kb, ah[fb][1]);                              \
        ldmx4((aLp) + arow0*TROW + kb, al[fb][0]);                              \
        ldmx4((aLp) + arow1*TROW + kb, al[fb][1]);                              \
        ldmx4((bHp) + brow*TROW + kb, bh[fb]);                                  \
        ldmx4((bLp) + brow*TROW + kb, bl[fb]);                                  \
    }

    for (int c = 0; c < nch; c++) {
        CP_WAIT0();
        __syncthreads();
        if (c + 1 < nch) LOAD_CHUNK(c+1, buf^1)
        uint32_t aH = sb + buf*BUFSZ;
        uint32_t aL = aH + ATSZ;
        uint32_t bH = aH + 2*ATSZ;
        uint32_t bL = aH + 3*ATSZ;
        LOAD_FRAGS(0, 0, aH, aL, bH, bL)
        #pragma unroll
        for (int kk = 0; kk < 4; kk++) {
            int cb = kk & 1;
            if (kk < 3) LOAD_FRAGS(kk+1, cb^1, aH, aL, bH, bL)
            #pragma unroll
            for (int mi = 0; mi < 2; mi++) {
                #pragma unroll
                for (int nj = 0; nj < 2; nj++) {
                    mma16816(acc[mi][nj], ah[cb][mi], bh[cb][nj], bh[cb][nj+2]);
                    mma16816(acc[mi][nj], ah[cb][mi], bl[cb][nj], bl[cb][nj+2]);
                    mma16816(acc[mi][nj], al[cb][mi], bh[cb][nj], bh[cb][nj+2]);
                }
            }
        }
        __syncthreads();
        buf ^= 1;
    }
    #undef LOAD_CHUNK
    #undef LOAD_FRAGS

    int cbase = bn + wn*16 + (lane & 3)*2;
    int rbase = bm + wm*32 + (lane >> 2);
    if (ksplit > 1) {
        float* Cp = C + (size_t)blockIdx.z * Mpad * N;
        #pragma unroll
        for (int mi = 0; mi < 2; mi++) {
            #pragma unroll
            for (int half = 0; half < 2; half++) {
                int r = rbase + mi*16 + half*8;
                if (r >= Mreal) continue;
                #pragma unroll
                for (int nj = 0; nj < 2; nj++) {
                    float2 v = make_float2(acc[mi][nj][half*2], acc[mi][nj][half*2+1]);
                    *(float2*)(Cp + (size_t)r*N + cbase + nj*8) = v;
                }
            }
        }
        return;
    }
    #pragma unroll
    for (int mi = 0; mi < 2; mi++) {
        #pragma unroll
        for (int half = 0; half < 2; half++) {
            int r = rbase + mi*16 + half*8;
            if (r >= Mreal) continue;
            int orow = r;
            if (remap) {
                int b2 = r / (HI*WI); int rr = r % (HI*WI);
                int hi2 = rr / WI, wi2 = rr % WI;
                orow = (b2*4 + (hi2&1)*2 + (wi2&1))*NPOS + (hi2>>1)*WO + (wi2>>1);
            }
            #pragma unroll
            for (int nj = 0; nj < 2; nj++) {
                int col = cbase + nj*8;
                float v0 = acc[mi][nj][half*2], v1 = acc[mi][nj][half*2+1];
                if (bias) { v0 += bias[col]; v1 += bias[col+1]; }
                if (act)  { v0 = gelu_exact(v0); v1 = gelu_exact(v1); }
                if (CS && col < 512) {
                    int pos = orow % NPOS;
                    int rr2 = (col & 31) >> 1;
                    float c = CS[pos*16 + rr2], s = SN[pos*16 + rr2];
                    float t0 = v0*c - v1*s;
                    v1 = v1*c + v0*s;
                    v0 = t0;
                }
                if (Oh) {
                    __nv_bfloat162 hv, lv;
                    split_hl(v0, hv.x, lv.x);
                    split_hl(v1, hv.y, lv.y);
                    *(__nv_bfloat162*)(Oh + (size_t)orow*N + col) = hv;
                    *(__nv_bfloat162*)(Ol + (size_t)orow*N + col) = lv;
                } else {
                    *(float2*)(C + (size_t)orow*N + col) = make_float2(v0, v1);
                }
            }
        }
    }
}

// ---------------- merged weight converter (9 segments) ----------------
struct CvtSegs {
    const float* src[9];
    bf16* hi[9];
    bf16* lo[9];
};
#define S0 16384
#define S1 16384
#define S2 16384
#define S3 32768
#define S4 32768
#define S5 98304
#define S6 32768
#define S7 98304
#define S8 98304
#define CVT_TOT (S0+S1+S2+S3+S4+S5+S6+S7+S8)

__global__ void cvt_all(CvtSegs segs) {
    int i = blockIdx.x*blockDim.x + threadIdx.x;
    if (i >= CVT_TOT) return;
    int seg, off = i;
    if      (off < S0) seg = 0;
    else if ((off -= S0) < S1) seg = 1;
    else if ((off -= S1) < S2) seg = 2;
    else if ((off -= S2) < S3) seg = 3;
    else if ((off -= S3) < S4) seg = 4;
    else if ((off -= S4) < S5) seg = 5;
    else if ((off -= S5) < S6) seg = 6;
    else if ((off -= S6) < S7) seg = 7;
    else { off -= S7; seg = 8; }
    float4 v = ((const float4*)segs.src[seg])[off];
    __nv_bfloat162 h0, h1, l0, l1;
    split_hl(v.x, h0.x, l0.x); split_hl(v.y, h0.y, l0.y);
    split_hl(v.z, h1.x, l1.x); split_hl(v.w, h1.y, l1.y);
    ((__nv_bfloat162*)segs.hi[seg])[2*off]   = h0;
    ((__nv_bfloat162*)segs.hi[seg])[2*off+1] = h1;
    ((__nv_bfloat162*)segs.lo[seg])[2*off]   = l0;
    ((__nv_bfloat162*)segs.lo[seg])[2*off+1] = l1;
}

// ---------------- warp-per-row LN over 256 (+ optional raw hi/lo out) ----------------
__global__ void ln_warp(const float* __restrict__ in, const float* __restrict__ gamma,
                        const float* __restrict__ beta,
                        bf16* __restrict__ oh, bf16* __restrict__ ol,
                        bf16* __restrict__ rh, bf16* __restrict__ rl,
                        int nrows) {
    int gw = (blockIdx.x * blockDim.x + threadIdx.x) >> 5;
    int lane = threadIdx.x & 31;
    if (gw >= nrows) return;
    const float4* row = (const float4*)(in + (size_t)gw * DD);
    float4 v0 = row[lane], v1 = row[lane + 32];
    if (rh) {
        __nv_bfloat162* hp = (__nv_bfloat162*)(rh + (size_t)gw * DD);
        __nv_bfloat162* lp = (__nv_bfloat162*)(rl + (size_t)gw * DD);
        __nv_bfloat162 h0, l0, h1, l1;
        split_hl(v0.x, h0.x, l0.x); split_hl(v0.y, h0.y, l0.y);
        split_hl(v0.z, h1.x, l1.x); split_hl(v0.w, h1.y, l1.y);
        hp[lane*2] = h0; hp[lane*2+1] = h1;
        lp[lane*2] = l0; lp[lane*2+1] = l1;
        split_hl(v1.x, h0.x, l0.x); split_hl(v1.y, h0.y, l0.y);
        split_hl(v1.z, h1.x, l1.x); split_hl(v1.w, h1.y, l1.y);
        hp[64+lane*2] = h0; hp[64+lane*2+1] = h1;
        lp[64+lane*2] = l0; lp[64+lane*2+1] = l1;
    }
    float s = v0.x+v0.y+v0.z+v0.w + v1.x+v1.y+v1.z+v1.w;
    #pragma unroll
    for (int o=16;o;o>>=1) s += __shfl_xor_sync(0xffffffffu, s, o);
    float mean = s * (1.f/256.f);
    float d[8] = {v0.x-mean, v0.y-mean, v0.z-mean, v0.w-mean,
                  v1.x-mean, v1.y-mean, v1.z-mean, v1.w-mean};
    float sq = 0.f;
    #pragma unroll
    for (int e=0;e<8;e++) sq += d[e]*d[e];
    #pragma unroll
    for (int o=16;o;o>>=1) sq += __shfl_xor_sync(0xffffffffu, sq, o);
    float inv = rsqrtf(sq * (1.f/256.f) + LN_EPS);
    float4 g0 = ((const float4*)gamma)[lane], g1 = ((const float4*)gamma)[lane+32];
    float4 b0 = ((const float4*)beta)[lane],  b1 = ((const float4*)beta)[lane+32];
    float y[8];
    y[0]=d[0]*inv*g0.x+b0.x; y[1]=d[1]*inv*g0.y+b0.y; y[2]=d[2]*inv*g0.z+b0.z; y[3]=d[3]*inv*g0.w+b0.w;
    y[4]=d[4]*inv*g1.x+b1.x; y[5]=d[5]*inv*g1.y+b1.y; y[6]=d[6]*inv*g1.z+b1.z; y[7]=d[7]*inv*g1.w+b1.w;
    __nv_bfloat162* hp = (__nv_bfloat162*)(oh + (size_t)gw * DD);
    __nv_bfloat162* lp = (__nv_bfloat162*)(ol + (size_t)gw * DD);
    #pragma unroll
    for (int q = 0; q < 4; q++) {
        __nv_bfloat162 hv, lv;
        split_hl(y[q*2],   hv.x, lv.x);
        split_hl(y[q*2+1], hv.y, lv.y);
        int idx = (q < 2) ? (lane*2 + q) : (64 + lane*2 + (q-2));
        hp[idx] = hv;
        lp[idx] = lv;
    }
}

// warp-level LN of an 8-element-per-lane fragment, then bf16 hi/lo store
__device__ __forceinline__ void ln_store_hl(float* y, const float* gamma, const float* beta,
                                            int lane, bf16* oh, bf16* ol, size_t rowoff) {
    float sm = 0.f;
    #pragma unroll
    for (int e=0;e<8;e++) sm += y[e];
    #pragma unroll
    for (int o=16;o;o>>=1) sm += __shfl_xor_sync(0xffffffffu, sm, o);
    float mean = sm * (1.f/256.f);
    float d[8], sq = 0.f;
    #pragma unroll
    for (int e=0;e<8;e++) { d[e] = y[e]-mean; sq += d[e]*d[e]; }
    #pragma unroll
    for (int o=16;o;o>>=1) sq += __shfl_xor_sync(0xffffffffu, sq, o);
    float inv = rsqrtf(sq * (1.f/256.f) + LN_EPS);
    float4 g0 = ((const float4*)gamma)[lane], g1 = ((const float4*)gamma)[lane+32];
    float4 b0 = ((const float4*)beta)[lane],  b1 = ((const float4*)beta)[lane+32];
    float z[8];
    z[0]=d[0]*inv*g0.x+b0.x; z[1]=d[1]*inv*g0.y+b0.y; z[2]=d[2]*inv*g0.z+b0.z; z[3]=d[3]*inv*g0.w+b0.w;
    z[4]=d[4]*inv*g1.x+b1.x; z[5]=d[5]*inv*g1.y+b1.y; z[6]=d[6]*inv*g1.z+b1.z; z[7]=d[7]*inv*g1.w+b1.w;
    __nv_bfloat162* hp = (__nv_bfloat162*)(oh + rowoff);
    __nv_bfloat162* lp = (__nv_bfloat162*)(ol + rowoff);
    #pragma unroll
    for (int q = 0; q < 4; q++) {
        __nv_bfloat162 hv, lv;
        split_hl(z[q*2],   hv.x, lv.x);
        split_hl(z[q*2+1], hv.y, lv.y);
        int idx = (q < 2) ? (lane*2 + q) : (64 + lane*2 + (q-2));
        hp[idx] = hv;
        lp[idx] = lv;
    }
}

// ---------------- combine(+bias) -> LN1 -> +res -> xout; then LN2 -> bf16 ----------------
__global__ void combine_ln2(const float* __restrict__ part, int s,
                            const float* __restrict__ bias,
                            const float* __restrict__ g1, const float* __restrict__ b1,
                            const float* __restrict__ res, float* __restrict__ outf,
                            const float* __restrict__ g2, const float* __restrict__ b2,
                            bf16* __restrict__ oh, bf16* __restrict__ ol,
                            int Mpad, int nrows) {
    int gw = (blockIdx.x * blockDim.x + threadIdx.x) >> 5;
    int lane = threadIdx.x & 31;
    if (gw >= nrows) return;
    float y[8];
    {
        const float4* p0 = (const float4*)(part + (size_t)gw * DD);
        float4 v0 = p0[lane], v1 = p0[lane+32];
        y[0]=v0.x; y[1]=v0.y; y[2]=v0.z; y[3]=v0.w;
        y[4]=v1.x; y[5]=v1.y; y[6]=v1.z; y[7]=v1.w;
        for (int z = 1; z < s; z++) {
            const float4* pz = (const float4*)(part + (size_t)z*Mpad*DD + (size_t)gw * DD);
            float4 w0 = pz[lane], w1 = pz[lane+32];
            y[0]+=w0.x; y[1]+=w0.y; y[2]+=w0.z; y[3]+=w0.w;
            y[4]+=w1.x; y[5]+=w1.y; y[6]+=w1.z; y[7]+=w1.w;
        }
    }
    if (bias) {
        float4 c0 = ((const float4*)bias)[lane], c1 = ((const float4*)bias)[lane+32];
        y[0]+=c0.x; y[1]+=c0.y; y[2]+=c0.z; y[3]+=c0.w;
        y[4]+=c1.x; y[5]+=c1.y; y[6]+=c1.z; y[7]+=c1.w;
    }
    float sm = 0.f;
    #pragma unroll
    for (int e=0;e<8;e++) sm += y[e];
    #pragma unroll
    for (int o=16;o;o>>=1) sm += __shfl_xor_sync(0xffffffffu, sm, o);
    float mean = sm * (1.f/256.f);
    float sq = 0.f;
    #pragma unroll
    for (int e=0;e<8;e++) { y[e] -= mean; sq += y[e]*y[e]; }
    #pragma unroll
    for (int o=16;o;o>>=1) sq += __shfl_xor_sync(0xffffffffu, sq, o);
    float inv = rsqrtf(sq * (1.f/256.f) + LN_EPS);
    float4 gg0 = ((const float4*)g1)[lane], gg1 = ((const float4*)g1)[lane+32];
    float4 bb0 = ((const float4*)b1)[lane], bb1 = ((const float4*)b1)[lane+32];
    y[0]=y[0]*inv*gg0.x+bb0.x; y[1]=y[1]*inv*gg0.y+bb0.y; y[2]=y[2]*inv*gg0.z+bb0.z; y[3]=y[3]*inv*gg0.w+bb0.w;
    y[4]=y[4]*inv*gg1.x+bb1.x; y[5]=y[5]*inv*gg1.y+bb1.y; y[6]=y[6]*inv*gg1.z+bb1.z; y[7]=y[7]*inv*gg1.w+bb1.w;
    if (res) {
        const float4* rr = (const float4*)(res + (size_t)gw * DD);
        float4 r0 = rr[lane], r1 = rr[lane+32];
        y[0]+=r0.x; y[1]+=r0.y; y[2]+=r0.z; y[3]+=r0.w;
        y[4]+=r1.x; y[5]+=r1.y; y[6]+=r1.z; y[7]+=r1.w;
    }
    float4* op = (float4*)(outf + (size_t)gw * DD);
    op[lane]    = make_float4(y[0],y[1],y[2],y[3]);
    op[lane+32] = make_float4(y[4],y[5],y[6],y[7]);
    ln_store_hl(y, g2, b2, lane, oh, ol, (size_t)gw * DD);
}

// ---------------- combine(+bias) -> +res -> xout; then LN -> bf16 ----------------
__global__ void combine_res_ln(const float* __restrict__ part, int s,
                               const float* __restrict__ bias, const float* __restrict__ res,
                               float* __restrict__ outf,
                               const float* __restrict__ g2, const float* __restrict__ b2,
                               bf16* __restrict__ oh, bf16* __restrict__ ol,
                               int Mpad, int nrows) {
    int gw = (blockIdx.x * blockDim.x + threadIdx.x) >> 5;
    int lane = threadIdx.x & 31;
    if (gw >= nrows) return;
    float y[8];
    {
        const float4* p0 = (const float4*)(part + (size_t)gw * DD);
        float4 v0 = p0[lane], v1 = p0[lane+32];
        y[0]=v0.x; y[1]=v0.y; y[2]=v0.z; y[3]=v0.w;
        y[4]=v1.x; y[5]=v1.y; y[6]=v1.z; y[7]=v1.w;
        for (int z = 1; z < s; z++) {
            const float4* pz = (const float4*)(part + (size_t)z*Mpad*DD + (size_t)gw * DD);
            float4 w0 = pz[lane], w1 = pz[lane+32];
            y[0]+=w0.x; y[1]+=w0.y; y[2]+=w0.z; y[3]+=w0.w;
            y[4]+=w1.x; y[5]+=w1.y; y[6]+=w1.z; y[7]+=w1.w;
        }
    }
    if (bias) {
        float4 c0 = ((const float4*)bias)[lane], c1 = ((const float4*)bias)[lane+32];
        y[0]+=c0.x; y[1]+=c0.y; y[2]+=c0.z; y[3]+=c0.w;
        y[4]+=c1.x; y[5]+=c1.y; y[6]+=c1.z; y[7]+=c1.w;
    }
    {
        const float4* rr = (const float4*)(res + (size_t)gw * DD);
        float4 r0 = rr[lane], r1 = rr[lane+32];
        y[0]+=r0.x; y[1]+=r0.y; y[2]+=r0.z; y[3]+=r0.w;
        y[4]+=r1.x; y[5]+=r1.y; y[6]+=r1.z; y[7]+=r1.w;
    }
    float4* op = (float4*)(outf + (size_t)gw * DD);
    op[lane]    = make_float4(y[0],y[1],y[2],y[3]);
    op[lane+32] = make_float4(y[4],y[5],y[6],y[7]);
    ln_store_hl(y, g2, b2, lane, oh, ol, (size_t)gw * DD);
}

// ---------------- plain split-K combine with epilogue ----------------
__global__ void combine_k(const float* __restrict__ part, int s,
                          const float* __restrict__ bias, const float* __restrict__ res,
                          float* __restrict__ out, int Mreal, int Mpad, int N, int act) {
    int i4 = blockIdx.x*blockDim.x + threadIdx.x;
    int tot = (Mreal*N) >> 2;
    if (i4 >= tot) return;
    size_t zs = ((size_t)Mpad*N) >> 2;
    float4 v = ((const float4*)part)[i4];
    for (int z = 1; z < s; z++) {
        float4 w = ((const float4*)part)[i4 + z*zs];
        v.x+=w.x; v.y+=w.y; v.z+=w.z; v.w+=w.w;
    }
    int col = (i4*4) % N;
    if (bias) {
        float4 bvv = *(const float4*)(bias + col);
        v.x+=bvv.x; v.y+=bvv.y; v.z+=bvv.z; v.w+=bvv.w;
    }
    if (act) { v.x=gelu_exact(v.x); v.y=gelu_exact(v.y); v.z=gelu_exact(v.z); v.w=gelu_exact(v.w); }
    if (res) {
        float4 rr = ((const float4*)res)[i4];
        v.x+=rr.x; v.y+=rr.y; v.z+=rr.z; v.w+=rr.w;
    }
    ((float4*)out)[i4] = v;
}

// ---------------- im2col (3x3 stride2 pad1), vectorized x4, bf16 hi/lo out ----------------
__global__ void im2col_hl(const float* __restrict__ x, bf16* __restrict__ oh, bf16* __restrict__ ol) {
    int idx = blockIdx.x*blockDim.x + threadIdx.x;
    const int total = NTOK*576;
    if (idx >= total) return;
    int c4 = idx % 576; int row = idx / 576;
    int b = row / NPOS; int p = row % NPOS;
    int i = p / WO, j = p % WO;
    int kk = c4 >> 6; int ic = (c4 & 63) * 4;
    int kh = kk / 3, kw = kk % 3;
    int hi = 2*i - 1 + kh, wi = 2*j - 1 + kw;
    float4 v = make_float4(0.f, 0.f, 0.f, 0.f);
    if (hi >= 0 && hi < HI && wi >= 0 && wi < WI)
        v = *(const float4*)(x + ((size_t)(b*(HI*WI) + hi*WI + wi))*DD + ic);
    __nv_bfloat162 h0, h1, l0, l1;
    split_hl(v.x, h0.x, l0.x); split_hl(v.y, h0.y, l0.y);
    split_hl(v.z, h1.x, l1.x); split_hl(v.w, h1.y, l1.y);
    size_t o = (size_t)row*2304 + kk*256 + ic;
    *(__nv_bfloat162*)(oh + o)     = h0;
    *(__nv_bfloat162*)(oh + o + 2) = h1;
    *(__nv_bfloat162*)(ol + o)     = l0;
    *(__nv_bfloat162*)(ol + o + 2) = l1;
}

__global__ void wseed_tr_hl(const float* __restrict__ w, bf16* __restrict__ oh, bf16* __restrict__ ol) {
    int idx = blockIdx.x*blockDim.x + threadIdx.x;
    if (idx >= DD*2304) return;
    int oc = idx / 2304; int c = idx % 2304;
    int kk = c >> 8; int ic = c & 255;
    float v = w[(size_t)oc*2304 + ic*9 + kk];
    split_hl(v, oh[idx], ol[idx]);
}

// ---------------- group NA (K=3): 4 groups merged, q read from split-K partials ----------------
__global__ void na3_attn4(const float* __restrict__ kg, const float* __restrict__ qsplit,
                          const float* __restrict__ rpb, const float* __restrict__ tau,
                          float* __restrict__ attn) {
    int blk = blockIdx.x;
    int p = blk % NPOS, b = blk / NPOS;
    int i = p / WO, j = p % WO;
    int t = threadIdx.x; int w = t >> 5; int lane = t & 31;
    __shared__ float kgs[4][256];
    __shared__ float logit[4][9];
    __shared__ float ev[4][9];
    if (t < 128) {
        int n = t >> 6, f = t & 63;
        ((float4*)kgs[n])[f]   = *(const float4*)(kg + ((size_t)(b*4+n)*NPOS + p)*DD + f*4);
        ((float4*)kgs[n+2])[f] = *(const float4*)(kg + ((size_t)(b*4+n+2)*NPOS + p)*DD + f*4);
    }
    int a = w / 3, c = w % 3;
    int si = min(max(i-1,0),25), sj = min(max(j-1,0),25);
    int np = (si+a)*WO + (sj+c);
    const float* q0 = qsplit + (size_t)(b*NPOS + np)*DD;
    const float* q1 = q0 + (size_t)NTOKP*DD;
    float qr[8];
    #pragma unroll
    for (int u=0;u<8;u++) qr[u] = q0[lane + 32*u] + q1[lane + 32*u];
    __syncthreads();
    #pragma unroll
    for (int n = 0; n < 4; n++) {
        float s = 0.f;
        #pragma unroll
        for (int u=0;u<8;u++) s = fmaf(qr[u], kgs[n][lane + 32*u], s);
        #pragma unroll
        for (int o=16;o;o>>=1) s += __shfl_xor_sync(0xffffffffu, s, o);
        if (lane==0) logit[n][w] = s + rpb[n*9 + w];
    }
    __syncthreads();
    if (t < 36) {
        int n = t/9, ac = t%9;
        float scale = expf(tau[0]);
        float m = -1e30f;
        #pragma unroll
        for (int u=0;u<9;u++) m = fmaxf(m, logit[n][u]*scale);
        ev[n][ac] = expf(logit[n][ac]*scale - m);
    }
    __syncthreads();
    if (t < 36) {
        int n = t/9, ac = t%9;
        float sum = 0.f;
        #pragma unroll
        for (int u=0;u<9;u++) sum += ev[n][u];
        attn[((size_t)(b*4+n)*NPOS + p)*9 + ac] = ev[n][ac]/sum + 1e-6f;
    }
}

// ---------------- deterministic column scatter-sum ----------------
__device__ __forceinline__ int inv_list(int s, int* lst) {
    if (s == 0)       { lst[0]=0;  lst[1]=1;  return 2; }
    else if (s == 25) { lst[0]=26; lst[1]=27; return 2; }
    else              { lst[0]=s+1;           return 1; }
}

__global__ void col_sum_k(const float* __restrict__ attn, float* __restrict__ col) {
    int idx = blockIdx.x*blockDim.x + threadIdx.x;
    if (idx >= BB*NPOS) return;
    int t = idx % NPOS, b = idx / NPOS;
    int ti = t / WO, tj = t % WO;
    float acc = 0.f;
    for (int a=0;a<3;a++) {
        int sr = ti - a; if (sr < 0 || sr > 25) continue;
        int il[2]; int ic = inv_list(sr, il);
        for (int c=0;c<3;c++) {
            int sc = tj - c; if (sc < 0 || sc > 25) continue;
            int jl[2]; int jc = inv_list(sc, jl);
            for (int ii=0; ii<ic; ii++)
                for (int jj=0; jj<jc; jj++) {
                    int pp = il[ii]*WO + jl[jj];
                    #pragma unroll
                    for (int n=0;n<4;n++)
                        acc += attn[((size_t)(b*4+n)*NPOS + pp)*9 + a*3 + c];
                }
        }
    }
    col[idx] = acc;
}

// ---------------- group NA AV + in-place residual + hi/lo out ----------------
__global__ void na3_av(const float* __restrict__ attn, const float* __restrict__ col,
                       const float* __restrict__ vg, float* __restrict__ xout,
                       bf16* __restrict__ oh, bf16* __restrict__ ol) {
    int blk = blockIdx.x;
    int p = blk % NPOS, b = blk / NPOS;
    int i = p / WO, j = p % WO;
    int t = threadIdx.x;
    __shared__ float wgt[4][9];
    __shared__ int npos[9];
    if (t < 9) {
        int a = t/3, c = t%3;
        int ni = min(max(i-1,0),25)+a, nj = min(max(j-1,0),25)+c;
        npos[t] = ni*WO + nj;
    }
    __syncthreads();
    if (t < 36) {
        int n = t/9, ac = t%9;
        float av = attn[((size_t)(b*4+n)*NPOS + p)*9 + ac];
        wgt[n][ac] = av / (col[b*NPOS + npos[ac]] + 1e-8f);
    }
    __syncthreads();
    float acc = xout[(size_t)blk*DD + t];
    #pragma unroll
    for (int n=0;n<4;n++) {
        const float* vb = vg + (size_t)(b*4+n)*NPOS*DD;
        #pragma unroll
        for (int ac=0;ac<9;ac++)
            acc = fmaf(wgt[n][ac], vb[(size_t)npos[ac]*DD + t], acc);
    }
    xout[(size_t)blk*DD + t] = acc;
    split_hl(acc, oh[(size_t)blk*DD + t], ol[(size_t)blk*DD + t]);
}

// ---------------- RoPE table ----------------
__global__ void rope_tab(float* __restrict__ cs, float* __restrict__ sn) {
    int idx = blockIdx.x*blockDim.x + threadIdx.x;
    if (idx >= NPOS*16) return;
    int pos = idx / 16, r = idx % 16;
    float f = expf(-((float)(2*r) / 32.f) * 9.210340371976184f);
    float ang = (float)pos * f;
    cs[idx] = cosf(ang);
    sn[idx] = sinf(ang);
}

// ---------------- block NA (K=7): row-blocked, smem-staged k/v window ----------------
#define NA7_SMEM ((2*6272 + 8*64) * 4)
__global__ void __launch_bounds__(256)
na7_row(const float* __restrict__ qkv, bf16* __restrict__ oh, bf16* __restrict__ ol) {
    extern __shared__ float sm7[];
    float* ks = sm7;
    float* vs = sm7 + 6272;
    float* wb = sm7 + 12544;
    int blk = blockIdx.x;
    int i = blk % 28; int bh = blk / 28; int h = bh & 7; int b = bh >> 3;
    int t = threadIdx.x, w = t >> 5, lane = t & 31;
    int si = min(max(i-3,0),21);
    for (int idx = t; idx < 1568; idx += 256) {
        int pos = idx >> 3, f = (idx & 7) * 4;
        int a = pos / 28, c = pos % 28;
        size_t g = ((size_t)(b*NPOS + (si+a)*WO + c))*768 + h*32 + f;
        *(float4*)(ks + pos*32 + f) = *(const float4*)(qkv + g + 256);
        *(float4*)(vs + pos*32 + f) = *(const float4*)(qkv + g + 512);
    }
    __syncthreads();
    for (int j = w; j < 28; j += 8) {
        int sj = min(max(j-3,0),21);
        int p = i*WO + j;
        float qd = qkv[((size_t)(b*NPOS + p))*768 + h*32 + lane];
        for (int nb = 0; nb < 49; nb++) {
            int a = nb / 7, c = nb % 7;
            float s = qd * ks[(a*28 + sj + c)*32 + lane];
            #pragma unroll
            for (int o=16;o;o>>=1) s += __shfl_xor_sync(0xffffffffu, s, o);
            if (lane == 0) wb[w*64 + nb] = s * 0.17677669529663687f;
        }
        __syncwarp();
        float m = -1e30f;
        for (int nb = lane; nb < 49; nb += 32) m = fmaxf(m, wb[w*64 + nb]);
        #pragma unroll
        for (int o=16;o;o>>=1) m = fmaxf(m, __shfl_xor_sync(0xffffffffu, m, o));
        float sum = 0.f;
        for (int nb = lane; nb < 49; nb += 32) {
            float e = expf(wb[w*64 + nb] - m);
            wb[w*64 + nb] = e;
            sum += e;
        }
        #pragma unroll
        for (int o=16;o;o>>=1) sum += __shfl_xor_sync(0xffffffffu, sum, o);
        __syncwarp();
        float inv = 1.f / sum;
        float acc = 0.f;
        for (int nb = 0; nb < 49; nb++) {
            int a = nb / 7, c = nb % 7;
            acc = fmaf(wb[w*64 + nb] * inv, vs[(a*28 + sj + c)*32 + lane], acc);
        }
        size_t o = ((size_t)(b*NPOS + p))*DD + h*32 + lane;
        split_hl(acc, oh[o], ol[o]);
        __syncwarp();
    }
}

// ---------------- host helpers ----------------
static inline void run_tc(const bf16* Ah, const bf16* Al, const bf16* Bh, const bf16* Bl,
                          const float* bias, float* C, bf16* Oh, bf16* Ol,
                          const float* cs, const float* sn,
                          int Mreal, int Mpad, int N, int K, int act, int remap, int ks) {
    dim3 grid(N/64, Mpad/64, ks);
    gemm_mma<<<grid, 256, GTC_SMEM>>>(Ah, Al, Bh, Bl, bias, C, Oh, Ol, cs, sn,
                                      Mreal, Mpad, N, K, act, remap, ks);
}

extern "C" void kernel_launch(void* const* d_in, const int* in_sizes, int n_in,
                              void* d_out, int out_size) {
    const float* x          = (const float*)d_in[0];
    const float* g_seed_w   = (const float*)d_in[1];
    const float* g_q_w      = (const float*)d_in[2];
    const float* g_k_w      = (const float*)d_in[3];
    const float* g_v_w      = (const float*)d_in[4];
    const float* g_mlp_w1   = (const float*)d_in[5];
    const float* g_mlp_b1   = (const float*)d_in[6];
    const float* g_mlp_w2   = (const float*)d_in[7];
    const float* g_mlp_b2   = (const float*)d_in[8];
    const float* g_ln_in_g  = (const float*)d_in[9];
    const float* g_ln_in_b  = (const float*)d_in[10];
    const float* g_ln_out_g = (const float*)d_in[11];
    const float* g_ln_out_b = (const float*)d_in[12];
    const float* g_tau      = (const float*)d_in[13];
    const float* g_rpb      = (const float*)d_in[14];
    const float* blk_ln1_g  = (const float*)d_in[15];
    const float* blk_ln1_b  = (const float*)d_in[16];
    const float* blk_qkv_w  = (const float*)d_in[17];
    const float* blk_proj_w = (const float*)d_in[18];
    const float* blk_proj_b = (const float*)d_in[19];
    const float* blk_ln2_g  = (const float*)d_in[20];
    const float* blk_ln2_b  = (const float*)d_in[21];
    const float* blk_mlp_w1 = (const float*)d_in[22];
    const float* blk_mlp_b1 = (const float*)d_in[23];
    const float* blk_mlp_w2 = (const float*)d_in[24];
    const float* blk_mlp_b2 = (const float*)d_in[25];
    float* out = (float*)d_out;

    cudaFuncSetAttribute(gemm_mma, cudaFuncAttributeMaxDynamicSharedMemorySize, GTC_SMEM);
    cudaFuncSetAttribute(na7_row, cudaFuncAttributeMaxDynamicSharedMemorySize, NA7_SMEM);

#define SYM(v, s) cudaGetSymbolAddress((void**)&v, s)
    float *xout, *buf2, *kg, *vg, *split, *attn, *colsum, *csb, *snb;
    SYM(xout,g_xout); SYM(buf2,g_buf2);
    SYM(kg,g_kg); SYM(vg,g_vg); SYM(split,g_split); SYM(attn,g_attn);
    SYM(colsum,g_colsum); SYM(csb,g_cos); SYM(snb,g_sin);
    bf16 *xh,*xl,*lnxh,*lnxl,*colh,*coll,*a1h,*a1l,*a2h,*a2l;
    SYM(xh,g_xh); SYM(xl,g_xl); SYM(lnxh,g_lnxh); SYM(lnxl,g_lnxl);
    SYM(colh,g_colh); SYM(coll,g_coll); SYM(a1h,g_a1h); SYM(a1l,g_a1l);
    SYM(a2h,g_a2h); SYM(a2l,g_a2l);
    bf16 *wsh,*wsl,*wqh,*wql,*wkh,*wkl,*wvh,*wvl,*m1h,*m1l,*m2h,*m2l;
    SYM(wsh,g_wsh); SYM(wsl,g_wsl); SYM(wqh,g_wqh); SYM(wql,g_wql);
    SYM(wkh,g_wkh); SYM(wkl,g_wkl); SYM(wvh,g_wvh); SYM(wvl,g_wvl);
    SYM(m1h,g_m1h); SYM(m1l,g_m1l); SYM(m2h,g_m2h); SYM(m2l,g_m2l);
    bf16 *qkvh,*qkvl,*pjh,*pjl,*bm1h,*bm1l,*bm2h,*bm2l;
    SYM(qkvh,g_qkvh); SYM(qkvl,g_qkvl); SYM(pjh,g_pjh); SYM(pjl,g_pjl);
    SYM(bm1h,g_bm1h); SYM(bm1l,g_bm1l); SYM(bm2h,g_bm2h); SYM(bm2l,g_bm2l);
#undef SYM

    // ---- weight conversions ----
    wseed_tr_hl<<<(DD*2304 + 255)/256, 256>>>(g_seed_w, wsh, wsl);
    {
        CvtSegs cs;
        cs.src[0]=g_q_w;      cs.hi[0]=wqh;  cs.lo[0]=wql;
        cs.src[1]=g_k_w;      cs.hi[1]=wkh;  cs.lo[1]=wkl;
        cs.src[2]=g_v_w;      cs.hi[2]=wvh;  cs.lo[2]=wvl;
        cs.src[3]=g_mlp_w1;   cs.hi[3]=m1h;  cs.lo[3]=m1l;
        cs.src[4]=g_mlp_w2;   cs.hi[4]=m2h;  cs.lo[4]=m2l;
        cs.src[5]=blk_qkv_w;  cs.hi[5]=qkvh; cs.lo[5]=qkvl;
        cs.src[6]=blk_proj_w; cs.hi[6]=pjh;  cs.lo[6]=pjl;
        cs.src[7]=blk_mlp_w1; cs.hi[7]=bm1h; cs.lo[7]=bm1l;
        cs.src[8]=blk_mlp_w2; cs.hi[8]=bm2h; cs.lo[8]=bm2l;
        cvt_all<<<(CVT_TOT + 255)/256, 256>>>(cs);
    }

    // ---- LN_in(x) + raw x hi/lo in one pass ----
    ln_warp<<<(NTOKIN + 7)/8, 256>>>(x, g_ln_in_g, g_ln_in_b, lnxh, lnxl, xh, xl, NTOKIN);
    run_tc(lnxh, lnxl, wkh, wkl, nullptr, kg, nullptr, nullptr, nullptr, nullptr,
           NTOKIN, NTOKIN, DD, DD, 0, 1, 1);
    run_tc(xh,   xl,   wvh, wvl, nullptr, vg, nullptr, nullptr, nullptr, nullptr,
           NTOKIN, NTOKIN, DD, DD, 0, 1, 1);

    // ---- seed conv ----
    im2col_hl<<<(NTOK*576 + 255)/256, 256>>>(x, colh, coll);
    run_tc(colh, coll, wsh, wsl, nullptr, split, nullptr, nullptr, nullptr, nullptr,
           NTOK, NTOKP, DD, 2304, 0, 0, 3);
    combine_ln2<<<(NTOK + 7)/8, 256>>>(split, 3, nullptr, g_ln_out_g, g_ln_out_b,
                                       nullptr, xout, g_ln_out_g, g_ln_out_b,
                                       a2h, a2l, NTOKP, NTOK);

    rope_tab<<<(NPOS*16 + 255)/256, 256>>>(csb, snb);

    // ---- 3 grouped-NA seeding iterations ----
    for (int it = 0; it < 3; it++) {
        run_tc(a2h, a2l, wqh, wql, nullptr, split, nullptr, nullptr, nullptr, nullptr,
               NTOK, NTOKP, DD, DD, 0, 0, 2);
        na3_attn4<<<NTOK, 288>>>(kg, split, g_rpb, g_tau, attn);
        col_sum_k<<<(BB*NPOS + 255)/256, 256>>>(attn, colsum);
        na3_av<<<NTOK, 256>>>(attn, colsum, vg, xout, a2h, a2l);
        run_tc(a2h, a2l, m1h, m1l, g_mlp_b1, nullptr, a1h, a1l, nullptr, nullptr,
               NTOK, NTOKP, 512, DD, 1, 0, 1);
        run_tc(a1h, a1l, m2h, m2l, nullptr, split, nullptr, nullptr, nullptr, nullptr,
               NTOK, NTOKP, DD, 512, 0, 0, 2);
        const float* g2 = (it < 2) ? g_ln_out_g : blk_ln1_g;
        const float* b2 = (it < 2) ? g_ln_out_b : blk_ln1_b;
        combine_ln2<<<(NTOK + 7)/8, 256>>>(split, 2, g_mlp_b2, g_ln_out_g, g_ln_out_b,
                                           xout, xout, g2, b2, a2h, a2l, NTOKP, NTOK);
    }

    // ---- 2 transformer blocks with 7x7 NA ----
    for (int l = 0; l < 2; l++) {
        run_tc(a2h, a2l, qkvh + (size_t)l*768*DD, qkvl + (size_t)l*768*DD,
               nullptr, buf2, nullptr, nullptr, csb, snb,
               NTOK, NTOKP, 768, DD, 0, 0, 1);
        na7_row<<<BB*HEADS*28, 256, NA7_SMEM>>>(buf2, a2h, a2l);
        run_tc(a2h, a2l, pjh + (size_t)l*DD*DD, pjl + (size_t)l*DD*DD,
               nullptr, split, nullptr, nullptr, nullptr, nullptr,
               NTOK, NTOKP, DD, DD, 0, 0, 2);
        combine_res_ln<<<(NTOK + 7)/8, 256>>>(split, 2, blk_proj_b + l*DD, xout, xout,
                                              blk_ln2_g + l*DD, blk_ln2_b + l*DD,
                                              a2h, a2l, NTOKP, NTOK);
        run_tc(a2h, a2l, bm1h + (size_t)l*768*DD, bm1l + (size_t)l*768*DD,
               blk_mlp_b1 + l*768, nullptr, a1h, a1l, nullptr, nullptr,
               NTOK, NTOKP, 768, DD, 1, 0, 1);
        run_tc(a1h, a1l, bm2h + (size_t)l*DD*768, bm2l + (size_t)l*DD*768,
               nullptr, split, nullptr, nullptr, nullptr, nullptr,
               NTOK, NTOKP, DD, 768, 0, 0, 2);
        if (l == 0) {
            combine_res_ln<<<(NTOK + 7)/8, 256>>>(split, 2, blk_mlp_b2, xout, xout,
                                                  blk_ln1_g + DD, blk_ln1_b + DD,
                                                  a2h, a2l, NTOKP, NTOK);
        } else {
            int tot4 = (NTOK*DD) >> 2;
            combine_k<<<(tot4 + 255)/256, 256>>>(split, 2, blk_mlp_b2 + DD, xout, out,
                                                 NTOK, NTOKP, DD, 0);
        }
    }
}

// round 15
// speedup vs baseline: 1.1643x; 1.1643x over previous
#include <cuda_runtime.h>
#include <cuda_fp16.h>
#include <math.h>
#include <stdint.h>

// ---------------- problem constants ----------------
#define BB 4
#define HI 56
#define WI 56
#define DD 256
#define HO 28
#define WO 28
#define NPOS 784
#define NTOK (BB*NPOS)     // 3136
#define NTOKP 3200
#define NTOKIN (BB*HI*WI)  // 12544
#define HEADS 8
#define LN_EPS 1e-5f

typedef __half hf;

// ---------------- scratch (device globals) ----------------
__device__ float g_xout  [NTOK*DD];
__device__ float g_buf2  [NTOK*768];
__device__ float g_kg    [BB*4*NPOS*DD];
__device__ float g_vg    [BB*4*NPOS*DD];
__device__ float g_split [3*NTOKP*DD];
__device__ float g_attn  [BB*4*NPOS*9];
__device__ float g_colsum[BB*NPOS];
__device__ float g_cos   [NPOS*16];
__device__ float g_sin   [NPOS*16];

// fp16 activation buffers (hi only) and weight hi/lo buffers
__device__ hf g_xh[NTOKIN*DD];
__device__ hf g_lnxh[NTOKIN*DD];
__device__ hf g_colh[NTOKP*2304];
__device__ hf g_a1h[NTOKP*768];
__device__ hf g_a2h[NTOKP*256];
__device__ hf g_wsh[DD*2304], g_wsl[DD*2304];
__device__ hf g_wqh[DD*DD],   g_wql[DD*DD];
__device__ hf g_wkh[DD*DD],   g_wkl[DD*DD];
__device__ hf g_wvh[DD*DD],   g_wvl[DD*DD];
__device__ hf g_m1h[512*DD],  g_m1l[512*DD];
__device__ hf g_m2h[DD*512],  g_m2l[DD*512];
__device__ hf g_qkvh[2*768*DD], g_qkvl[2*768*DD];
__device__ hf g_pjh[2*DD*DD],   g_pjl[2*DD*DD];
__device__ hf g_bm1h[2*768*DD], g_bm1l[2*768*DD];
__device__ hf g_bm2h[2*DD*768], g_bm2l[2*DD*768];

// ---------------- helpers ----------------
__device__ __forceinline__ uint32_t smem_u32(const void* p) {
    uint32_t a;
    asm("{ .reg .u64 t; cvta.to.shared.u64 t, %1; cvt.u32.u64 %0, t; }" : "=r"(a) : "l"(p));
    return a;
}
__device__ __forceinline__ float gelu_exact(float x) {
    return 0.5f * x * (1.f + erff(x * 0.70710678118654752f));
}
__device__ __forceinline__ void cp16(uint32_t saddr, const void* gaddr) {
    asm volatile("cp.async.cg.shared.global [%0], [%1], 16;" :: "r"(saddr), "l"(gaddr));
}
#define CP_COMMIT() asm volatile("cp.async.commit_group;" ::: "memory")
#define CP_WAIT0()  asm volatile("cp.async.wait_group 0;" ::: "memory")

__device__ __forceinline__ void ldmx4(uint32_t addr, uint32_t* r) {
    asm volatile("ldmatrix.sync.aligned.m8n8.x4.shared.b16 {%0,%1,%2,%3}, [%4];"
        : "=r"(r[0]), "=r"(r[1]), "=r"(r[2]), "=r"(r[3]) : "r"(addr));
}
__device__ __forceinline__ void mma16816(float* d, const uint32_t* a, uint32_t b0, uint32_t b1) {
    asm volatile("mma.sync.aligned.m16n8k16.row.col.f32.f16.f16.f32 "
        "{%0,%1,%2,%3}, {%4,%5,%6,%7}, {%8,%9}, {%0,%1,%2,%3};"
        : "+f"(d[0]), "+f"(d[1]), "+f"(d[2]), "+f"(d[3])
        : "r"(a[0]), "r"(a[1]), "r"(a[2]), "r"(a[3]), "r"(b0), "r"(b1));
}
// weight hi/lo split
__device__ __forceinline__ void split_hl(float v, hf& h, hf& l) {
    h = __float2half(v);
    l = __float2half(v - __half2float(h));
}

// ---------------- tensor-core GEMM (mma.sync fp16, 2-pass: A*Bh + A*Bl) ----------------
// Tile M=64, N=64, K-chunk 64; tiles: A, Bh, Bl each 64x144B.
// BUFSZ = 3*9216 = 27648; double-buffered 55296 => 4 CTAs/SM.
#define TROW 144
#define ATSZ (64*TROW)          // 9216
#define BUFSZ (3*ATSZ)          // 27648
#define GTC_SMEM (2*BUFSZ)      // 55296

__global__ void __launch_bounds__(256, 4)
gemm_mma(const hf* __restrict__ Ah, const hf* __restrict__ Bh, const hf* __restrict__ Bl,
         const float* __restrict__ bias, float* __restrict__ C,
         hf* __restrict__ Oh,
         const float* __restrict__ CS, const float* __restrict__ SN,
         int Mreal, int Mpad, int N, int K, int act, int remap, int ksplit) {
    extern __shared__ char smraw[];
    uint32_t sb = smem_u32(smraw);
    int tid = threadIdx.x, wid = tid >> 5, lane = tid & 31;
    int wm = wid >> 2, wn = wid & 3;          // 2 x 4 warps, warp tile 32x16
    int bm = blockIdx.y * 64, bn = blockIdx.x * 64;
    int kper = K / ksplit;
    int kbase = blockIdx.z * kper;
    int nch = kper / 64;

    const hf* srcA = Ah + (size_t)bm*K;
    const hf* srcB[2] = { Bh + (size_t)bn*K, Bl + (size_t)bn*K };

    // per chunk: each tile = 64 rows x 8 segs = 512 f4 -> 2/thread
    #define LOAD_CHUNK(c, b) {                                                  \
        int k0 = kbase + (c)*64;                                                \
        uint32_t dbase = sb + (b)*BUFSZ;                                        \
        _Pragma("unroll")                                                       \
        for (int u = 0; u < 2; u++) {                                           \
            int idx = tid + u*256;                                              \
            int row = idx >> 3, seg = idx & 7;                                  \
            cp16(dbase + row*TROW + seg*16,                                     \
                 srcA + (size_t)row*K + k0 + seg*8);                            \
        }                                                                       \
        _Pragma("unroll")                                                       \
        for (int s = 0; s < 2; s++) {                                           \
            uint32_t dst = dbase + ATSZ + s*ATSZ;                               \
            _Pragma("unroll")                                                   \
            for (int u = 0; u < 2; u++) {                                       \
                int idx = tid + u*256;                                          \
                int brow = idx >> 3, bseg = idx & 7;                            \
                cp16(dst + brow*TROW + bseg*16,                                 \
                     srcB[s] + (size_t)brow*K + k0 + bseg*8);                   \
            }                                                                   \
        }                                                                       \
        CP_COMMIT();                                                            \
    }

    float acc[2][2][4];
    #pragma unroll
    for (int i=0;i<2;i++)
        #pragma unroll
        for (int j=0;j<2;j++)
            #pragma unroll
            for (int e=0;e<4;e++) acc[i][j][e] = 0.f;

    LOAD_CHUNK(0, 0)
    int buf = 0;
    int lr16 = lane & 15, lh = lane >> 4;

    for (int c = 0; c < nch; c++) {
        CP_WAIT0();
        __syncthreads();
        if (c + 1 < nch) LOAD_CHUNK(c+1, buf^1)
        uint32_t aA = sb + buf*BUFSZ;
        uint32_t bH = aA + ATSZ;
        uint32_t bL = aA + 2*ATSZ;
        #pragma unroll
        for (int kk = 0; kk < 4; kk++) {
            uint32_t ah[2][4], bh[4], bl[4];
            int kb = kk*32 + lh*16;
            #pragma unroll
            for (int mi = 0; mi < 2; mi++) {
                int row = wm*32 + mi*16 + lr16;
                ldmx4(aA + row*TROW + kb, ah[mi]);
            }
            {
                int row = wn*16 + lr16;
                ldmx4(bH + row*TROW + kb, bh);
                ldmx4(bL + row*TROW + kb, bl);
            }
            #pragma unroll
            for (int mi = 0; mi < 2; mi++) {
                #pragma unroll
                for (int nj = 0; nj < 2; nj++) {
                    mma16816(acc[mi][nj], ah[mi], bh[nj], bh[nj+2]);
                    mma16816(acc[mi][nj], ah[mi], bl[nj], bl[nj+2]);
                }
            }
        }
        __syncthreads();
        buf ^= 1;
    }
    #undef LOAD_CHUNK

    int cbase = bn + wn*16 + (lane & 3)*2;
    int rbase = bm + wm*32 + (lane >> 2);
    if (ksplit > 1) {
        float* Cp = C + (size_t)blockIdx.z * Mpad * N;
        #pragma unroll
        for (int mi = 0; mi < 2; mi++) {
            #pragma unroll
            for (int half = 0; half < 2; half++) {
                int r = rbase + mi*16 + half*8;
                if (r >= Mreal) continue;
                #pragma unroll
                for (int nj = 0; nj < 2; nj++) {
                    float2 v = make_float2(acc[mi][nj][half*2], acc[mi][nj][half*2+1]);
                    *(float2*)(Cp + (size_t)r*N + cbase + nj*8) = v;
                }
            }
        }
        return;
    }
    #pragma unroll
    for (int mi = 0; mi < 2; mi++) {
        #pragma unroll
        for (int half = 0; half < 2; half++) {
            int r = rbase + mi*16 + half*8;
            if (r >= Mreal) continue;
            int orow = r;
            if (remap) {
                int b2 = r / (HI*WI); int rr = r % (HI*WI);
                int hi2 = rr / WI, wi2 = rr % WI;
                orow = (b2*4 + (hi2&1)*2 + (wi2&1))*NPOS + (hi2>>1)*WO + (wi2>>1);
            }
            #pragma unroll
            for (int nj = 0; nj < 2; nj++) {
                int col = cbase + nj*8;
                float v0 = acc[mi][nj][half*2], v1 = acc[mi][nj][half*2+1];
                if (bias) { v0 += bias[col]; v1 += bias[col+1]; }
                if (act)  { v0 = gelu_exact(v0); v1 = gelu_exact(v1); }
                if (CS && col < 512) {
                    int pos = orow % NPOS;
                    int rr2 = (col & 31) >> 1;
                    float c = CS[pos*16 + rr2], s = SN[pos*16 + rr2];
                    float t0 = v0*c - v1*s;
                    v1 = v1*c + v0*s;
                    v0 = t0;
                }
                if (Oh) {
                    __half2 hv;
                    hv.x = __float2half(v0);
                    hv.y = __float2half(v1);
                    *(__half2*)(Oh + (size_t)orow*N + col) = hv;
                } else {
                    *(float2*)(C + (size_t)orow*N + col) = make_float2(v0, v1);
                }
            }
        }
    }
}

// ---------------- merged weight converter (9 segments) ----------------
struct CvtSegs {
    const float* src[9];
    hf* hi[9];
    hf* lo[9];
};
#define S0 16384
#define S1 16384
#define S2 16384
#define S3 32768
#define S4 32768
#define S5 98304
#define S6 32768
#define S7 98304
#define S8 98304
#define CVT_TOT (S0+S1+S2+S3+S4+S5+S6+S7+S8)

__global__ void cvt_all(CvtSegs segs) {
    int i = blockIdx.x*blockDim.x + threadIdx.x;
    if (i >= CVT_TOT) return;
    int seg, off = i;
    if      (off < S0) seg = 0;
    else if ((off -= S0) < S1) seg = 1;
    else if ((off -= S1) < S2) seg = 2;
    else if ((off -= S2) < S3) seg = 3;
    else if ((off -= S3) < S4) seg = 4;
    else if ((off -= S4) < S5) seg = 5;
    else if ((off -= S5) < S6) seg = 6;
    else if ((off -= S6) < S7) seg = 7;
    else { off -= S7; seg = 8; }
    float4 v = ((const float4*)segs.src[seg])[off];
    __half2 h0, h1, l0, l1;
    split_hl(v.x, h0.x, l0.x); split_hl(v.y, h0.y, l0.y);
    split_hl(v.z, h1.x, l1.x); split_hl(v.w, h1.y, l1.y);
    ((__half2*)segs.hi[seg])[2*off]   = h0;
    ((__half2*)segs.hi[seg])[2*off+1] = h1;
    ((__half2*)segs.lo[seg])[2*off]   = l0;
    ((__half2*)segs.lo[seg])[2*off+1] = l1;
}

// ---------------- warp-per-row LN over 256 (+ optional raw fp16 out) ----------------
__global__ void ln_warp(const float* __restrict__ in, const float* __restrict__ gamma,
                        const float* __restrict__ beta,
                        hf* __restrict__ oh, hf* __restrict__ rh, int nrows) {
    int gw = (blockIdx.x * blockDim.x + threadIdx.x) >> 5;
    int lane = threadIdx.x & 31;
    if (gw >= nrows) return;
    const float4* row = (const float4*)(in + (size_t)gw * DD);
    float4 v0 = row[lane], v1 = row[lane + 32];
    if (rh) {
        __half2* hp = (__half2*)(rh + (size_t)gw * DD);
        __half2 h0, h1;
        h0.x = __float2half(v0.x); h0.y = __float2half(v0.y);
        h1.x = __float2half(v0.z); h1.y = __float2half(v0.w);
        hp[lane*2] = h0; hp[lane*2+1] = h1;
        h0.x = __float2half(v1.x); h0.y = __float2half(v1.y);
        h1.x = __float2half(v1.z); h1.y = __float2half(v1.w);
        hp[64+lane*2] = h0; hp[64+lane*2+1] = h1;
    }
    float s = v0.x+v0.y+v0.z+v0.w + v1.x+v1.y+v1.z+v1.w;
    #pragma unroll
    for (int o=16;o;o>>=1) s += __shfl_xor_sync(0xffffffffu, s, o);
    float mean = s * (1.f/256.f);
    float d[8] = {v0.x-mean, v0.y-mean, v0.z-mean, v0.w-mean,
                  v1.x-mean, v1.y-mean, v1.z-mean, v1.w-mean};
    float sq = 0.f;
    #pragma unroll
    for (int e=0;e<8;e++) sq += d[e]*d[e];
    #pragma unroll
    for (int o=16;o;o>>=1) sq += __shfl_xor_sync(0xffffffffu, sq, o);
    float inv = rsqrtf(sq * (1.f/256.f) + LN_EPS);
    float4 g0 = ((const float4*)gamma)[lane], g1 = ((const float4*)gamma)[lane+32];
    float4 b0 = ((const float4*)beta)[lane],  b1 = ((const float4*)beta)[lane+32];
    float y[8];
    y[0]=d[0]*inv*g0.x+b0.x; y[1]=d[1]*inv*g0.y+b0.y; y[2]=d[2]*inv*g0.z+b0.z; y[3]=d[3]*inv*g0.w+b0.w;
    y[4]=d[4]*inv*g1.x+b1.x; y[5]=d[5]*inv*g1.y+b1.y; y[6]=d[6]*inv*g1.z+b1.z; y[7]=d[7]*inv*g1.w+b1.w;
    __half2* hp = (__half2*)(oh + (size_t)gw * DD);
    #pragma unroll
    for (int q = 0; q < 4; q++) {
        __half2 hv;
        hv.x = __float2half(y[q*2]);
        hv.y = __float2half(y[q*2+1]);
        int idx = (q < 2) ? (lane*2 + q) : (64 + lane*2 + (q-2));
        hp[idx] = hv;
    }
}

// warp-level LN of an 8-element-per-lane fragment, then fp16 store
__device__ __forceinline__ void ln_store_h(float* y, const float* gamma, const float* beta,
                                           int lane, hf* oh, size_t rowoff) {
    float sm = 0.f;
    #pragma unroll
    for (int e=0;e<8;e++) sm += y[e];
    #pragma unroll
    for (int o=16;o;o>>=1) sm += __shfl_xor_sync(0xffffffffu, sm, o);
    float mean = sm * (1.f/256.f);
    float d[8], sq = 0.f;
    #pragma unroll
    for (int e=0;e<8;e++) { d[e] = y[e]-mean; sq += d[e]*d[e]; }
    #pragma unroll
    for (int o=16;o;o>>=1) sq += __shfl_xor_sync(0xffffffffu, sq, o);
    float inv = rsqrtf(sq * (1.f/256.f) + LN_EPS);
    float4 g0 = ((const float4*)gamma)[lane], g1 = ((const float4*)gamma)[lane+32];
    float4 b0 = ((const float4*)beta)[lane],  b1 = ((const float4*)beta)[lane+32];
    float z[8];
    z[0]=d[0]*inv*g0.x+b0.x; z[1]=d[1]*inv*g0.y+b0.y; z[2]=d[2]*inv*g0.z+b0.z; z[3]=d[3]*inv*g0.w+b0.w;
    z[4]=d[4]*inv*g1.x+b1.x; z[5]=d[5]*inv*g1.y+b1.y; z[6]=d[6]*inv*g1.z+b1.z; z[7]=d[7]*inv*g1.w+b1.w;
    __half2* hp = (__half2*)(oh + rowoff);
    #pragma unroll
    for (int q = 0; q < 4; q++) {
        __half2 hv;
        hv.x = __float2half(z[q*2]);
        hv.y = __float2half(z[q*2+1]);
        int idx = (q < 2) ? (lane*2 + q) : (64 + lane*2 + (q-2));
        hp[idx] = hv;
    }
}

// ---------------- combine(+bias) -> LN1 -> +res -> xout; then LN2 -> fp16 ----------------
__global__ void combine_ln2(const float* __restrict__ part, int s,
                            const float* __restrict__ bias,
                            const float* __restrict__ g1, const float* __restrict__ b1,
                            const float* __restrict__ res, float* __restrict__ outf,
                            const float* __restrict__ g2, const float* __restrict__ b2,
                            hf* __restrict__ oh, int Mpad, int nrows) {
    int gw = (blockIdx.x * blockDim.x + threadIdx.x) >> 5;
    int lane = threadIdx.x & 31;
    if (gw >= nrows) return;
    float y[8];
    {
        const float4* p0 = (const float4*)(part + (size_t)gw * DD);
        float4 v0 = p0[lane], v1 = p0[lane+32];
        y[0]=v0.x; y[1]=v0.y; y[2]=v0.z; y[3]=v0.w;
        y[4]=v1.x; y[5]=v1.y; y[6]=v1.z; y[7]=v1.w;
        for (int z = 1; z < s; z++) {
            const float4* pz = (const float4*)(part + (size_t)z*Mpad*DD + (size_t)gw * DD);
            float4 w0 = pz[lane], w1 = pz[lane+32];
            y[0]+=w0.x; y[1]+=w0.y; y[2]+=w0.z; y[3]+=w0.w;
            y[4]+=w1.x; y[5]+=w1.y; y[6]+=w1.z; y[7]+=w1.w;
        }
    }
    if (bias) {
        float4 c0 = ((const float4*)bias)[lane], c1 = ((const float4*)bias)[lane+32];
        y[0]+=c0.x; y[1]+=c0.y; y[2]+=c0.z; y[3]+=c0.w;
        y[4]+=c1.x; y[5]+=c1.y; y[6]+=c1.z; y[7]+=c1.w;
    }
    float sm = 0.f;
    #pragma unroll
    for (int e=0;e<8;e++) sm += y[e];
    #pragma unroll
    for (int o=16;o;o>>=1) sm += __shfl_xor_sync(0xffffffffu, sm, o);
    float mean = sm * (1.f/256.f);
    float sq = 0.f;
    #pragma unroll
    for (int e=0;e<8;e++) { y[e] -= mean; sq += y[e]*y[e]; }
    #pragma unroll
    for (int o=16;o;o>>=1) sq += __shfl_xor_sync(0xffffffffu, sq, o);
    float inv = rsqrtf(sq * (1.f/256.f) + LN_EPS);
    float4 gg0 = ((const float4*)g1)[lane], gg1 = ((const float4*)g1)[lane+32];
    float4 bb0 = ((const float4*)b1)[lane], bb1 = ((const float4*)b1)[lane+32];
    y[0]=y[0]*inv*gg0.x+bb0.x; y[1]=y[1]*inv*gg0.y+bb0.y; y[2]=y[2]*inv*gg0.z+bb0.z; y[3]=y[3]*inv*gg0.w+bb0.w;
    y[4]=y[4]*inv*gg1.x+bb1.x; y[5]=y[5]*inv*gg1.y+bb1.y; y[6]=y[6]*inv*gg1.z+bb1.z; y[7]=y[7]*inv*gg1.w+bb1.w;
    if (res) {
        const float4* rr = (const float4*)(res + (size_t)gw * DD);
        float4 r0 = rr[lane], r1 = rr[lane+32];
        y[0]+=r0.x; y[1]+=r0.y; y[2]+=r0.z; y[3]+=r0.w;
        y[4]+=r1.x; y[5]+=r1.y; y[6]+=r1.z; y[7]+=r1.w;
    }
    float4* op = (float4*)(outf + (size_t)gw * DD);
    op[lane]    = make_float4(y[0],y[1],y[2],y[3]);
    op[lane+32] = make_float4(y[4],y[5],y[6],y[7]);
    ln_store_h(y, g2, b2, lane, oh, (size_t)gw * DD);
}

// ---------------- combine(+bias) -> +res -> xout; then LN -> fp16 ----------------
__global__ void combine_res_ln(const float* __restrict__ part, int s,
                               const float* __restrict__ bias, const float* __restrict__ res,
                               float* __restrict__ outf,
                               const float* __restrict__ g2, const float* __restrict__ b2,
                               hf* __restrict__ oh, int Mpad, int nrows) {
    int gw = (blockIdx.x * blockDim.x + threadIdx.x) >> 5;
    int lane = threadIdx.x & 31;
    if (gw >= nrows) return;
    float y[8];
    {
        const float4* p0 = (const float4*)(part + (size_t)gw * DD);
        float4 v0 = p0[lane], v1 = p0[lane+32];
        y[0]=v0.x; y[1]=v0.y; y[2]=v0.z; y[3]=v0.w;
        y[4]=v1.x; y[5]=v1.y; y[6]=v1.z; y[7]=v1.w;
        for (int z = 1; z < s; z++) {
            const float4* pz = (const float4*)(part + (size_t)z*Mpad*DD + (size_t)gw * DD);
            float4 w0 = pz[lane], w1 = pz[lane+32];
            y[0]+=w0.x; y[1]+=w0.y; y[2]+=w0.z; y[3]+=w0.w;
            y[4]+=w1.x; y[5]+=w1.y; y[6]+=w1.z; y[7]+=w1.w;
        }
    }
    if (bias) {
        float4 c0 = ((const float4*)bias)[lane], c1 = ((const float4*)bias)[lane+32];
        y[0]+=c0.x; y[1]+=c0.y; y[2]+=c0.z; y[3]+=c0.w;
        y[4]+=c1.x; y[5]+=c1.y; y[6]+=c1.z; y[7]+=c1.w;
    }
    {
        const float4* rr = (const float4*)(res + (size_t)gw * DD);
        float4 r0 = rr[lane], r1 = rr[lane+32];
        y[0]+=r0.x; y[1]+=r0.y; y[2]+=r0.z; y[3]+=r0.w;
        y[4]+=r1.x; y[5]+=r1.y; y[6]+=r1.z; y[7]+=r1.w;
    }
    float4* op = (float4*)(outf + (size_t)gw * DD);
    op[lane]    = make_float4(y[0],y[1],y[2],y[3]);
    op[lane+32] = make_float4(y[4],y[5],y[6],y[7]);
    ln_store_h(y, g2, b2, lane, oh, (size_t)gw * DD);
}

// ---------------- plain split-K combine with epilogue ----------------
__global__ void combine_k(const float* __restrict__ part, int s,
                          const float* __restrict__ bias, const float* __restrict__ res,
                          float* __restrict__ out, int Mreal, int Mpad, int N, int act) {
    int i4 = blockIdx.x*blockDim.x + threadIdx.x;
    int tot = (Mreal*N) >> 2;
    if (i4 >= tot) return;
    size_t zs = ((size_t)Mpad*N) >> 2;
    float4 v = ((const float4*)part)[i4];
    for (int z = 1; z < s; z++) {
        float4 w = ((const float4*)part)[i4 + z*zs];
        v.x+=w.x; v.y+=w.y; v.z+=w.z; v.w+=w.w;
    }
    int col = (i4*4) % N;
    if (bias) {
        float4 bvv = *(const float4*)(bias + col);
        v.x+=bvv.x; v.y+=bvv.y; v.z+=bvv.z; v.w+=bvv.w;
    }
    if (act) { v.x=gelu_exact(v.x); v.y=gelu_exact(v.y); v.z=gelu_exact(v.z); v.w=gelu_exact(v.w); }
    if (res) {
        float4 rr = ((const float4*)res)[i4];
        v.x+=rr.x; v.y+=rr.y; v.z+=rr.z; v.w+=rr.w;
    }
    ((float4*)out)[i4] = v;
}

// ---------------- im2col (3x3 stride2 pad1), vectorized x4, fp16 out ----------------
__global__ void im2col_h(const float* __restrict__ x, hf* __restrict__ oh) {
    int idx = blockIdx.x*blockDim.x + threadIdx.x;
    const int total = NTOK*576;
    if (idx >= total) return;
    int c4 = idx % 576; int row = idx / 576;
    int b = row / NPOS; int p = row % NPOS;
    int i = p / WO, j = p % WO;
    int kk = c4 >> 6; int ic = (c4 & 63) * 4;
    int kh = kk / 3, kw = kk % 3;
    int hi = 2*i - 1 + kh, wi = 2*j - 1 + kw;
    float4 v = make_float4(0.f, 0.f, 0.f, 0.f);
    if (hi >= 0 && hi < HI && wi >= 0 && wi < WI)
        v = *(const float4*)(x + ((size_t)(b*(HI*WI) + hi*WI + wi))*DD + ic);
    __half2 h0, h1;
    h0.x = __float2half(v.x); h0.y = __float2half(v.y);
    h1.x = __float2half(v.z); h1.y = __float2half(v.w);
    size_t o = (size_t)row*2304 + kk*256 + ic;
    *(__half2*)(oh + o)     = h0;
    *(__half2*)(oh + o + 2) = h1;
}

// seed weight (oc,ic,kh,kw) -> [oc][kk*256+ic] fp16 hi/lo
__global__ void wseed_tr_hl(const float* __restrict__ w, hf* __restrict__ oh, hf* __restrict__ ol) {
    int idx = blockIdx.x*blockDim.x + threadIdx.x;
    if (idx >= DD*2304) return;
    int oc = idx / 2304; int c = idx % 2304;
    int kk = c >> 8; int ic = c & 255;
    float v = w[(size_t)oc*2304 + ic*9 + kk];
    split_hl(v, oh[idx], ol[idx]);
}

// ---------------- group NA (K=3): 4 groups merged, q read from split-K partials ----------------
__global__ void na3_attn4(const float* __restrict__ kg, const float* __restrict__ qsplit,
                          const float* __restrict__ rpb, const float* __restrict__ tau,
                          float* __restrict__ attn) {
    int blk = blockIdx.x;
    int p = blk % NPOS, b = blk / NPOS;
    int i = p / WO, j = p % WO;
    int t = threadIdx.x; int w = t >> 5; int lane = t & 31;
    __shared__ float kgs[4][256];
    __shared__ float logit[4][9];
    __shared__ float ev[4][9];
    if (t < 128) {
        int n = t >> 6, f = t & 63;
        ((float4*)kgs[n])[f]   = *(const float4*)(kg + ((size_t)(b*4+n)*NPOS + p)*DD + f*4);
        ((float4*)kgs[n+2])[f] = *(const float4*)(kg + ((size_t)(b*4+n+2)*NPOS + p)*DD + f*4);
    }
    int a = w / 3, c = w % 3;
    int si = min(max(i-1,0),25), sj = min(max(j-1,0),25);
    int np = (si+a)*WO + (sj+c);
    const float* q0 = qsplit + (size_t)(b*NPOS + np)*DD;
    const float* q1 = q0 + (size_t)NTOKP*DD;
    float qr[8];
    #pragma unroll
    for (int u=0;u<8;u++) qr[u] = q0[lane + 32*u] + q1[lane + 32*u];
    __syncthreads();
    #pragma unroll
    for (int n = 0; n < 4; n++) {
        float s = 0.f;
        #pragma unroll
        for (int u=0;u<8;u++) s = fmaf(qr[u], kgs[n][lane + 32*u], s);
        #pragma unroll
        for (int o=16;o;o>>=1) s += __shfl_xor_sync(0xffffffffu, s, o);
        if (lane==0) logit[n][w] = s + rpb[n*9 + w];
    }
    __syncthreads();
    if (t < 36) {
        int n = t/9, ac = t%9;
        float scale = expf(tau[0]);
        float m = -1e30f;
        #pragma unroll
        for (int u=0;u<9;u++) m = fmaxf(m, logit[n][u]*scale);
        ev[n][ac] = expf(logit[n][ac]*scale - m);
    }
    __syncthreads();
    if (t < 36) {
        int n = t/9, ac = t%9;
        float sum = 0.f;
        #pragma unroll
        for (int u=0;u<9;u++) sum += ev[n][u];
        attn[((size_t)(b*4+n)*NPOS + p)*9 + ac] = ev[n][ac]/sum + 1e-6f;
    }
}

// ---------------- deterministic column scatter-sum ----------------
__device__ __forceinline__ int inv_list(int s, int* lst) {
    if (s == 0)       { lst[0]=0;  lst[1]=1;  return 2; }
    else if (s == 25) { lst[0]=26; lst[1]=27; return 2; }
    else              { lst[0]=s+1;           return 1; }
}

__global__ void col_sum_k(const float* __restrict__ attn, float* __restrict__ col) {
    int idx = blockIdx.x*blockDim.x + threadIdx.x;
    if (idx >= BB*NPOS) return;
    int t = idx % NPOS, b = idx / NPOS;
    int ti = t / WO, tj = t % WO;
    float acc = 0.f;
    for (int a=0;a<3;a++) {
        int sr = ti - a; if (sr < 0 || sr > 25) continue;
        int il[2]; int ic = inv_list(sr, il);
        for (int c=0;c<3;c++) {
            int sc = tj - c; if (sc < 0 || sc > 25) continue;
            int jl[2]; int jc = inv_list(sc, jl);
            for (int ii=0; ii<ic; ii++)
                for (int jj=0; jj<jc; jj++) {
                    int pp = il[ii]*WO + jl[jj];
                    #pragma unroll
                    for (int n=0;n<4;n++)
                        acc += attn[((size_t)(b*4+n)*NPOS + pp)*9 + a*3 + c];
                }
        }
    }
    col[idx] = acc;
}

// ---------------- group NA AV + in-place residual + fp16 out ----------------
__global__ void na3_av(const float* __restrict__ attn, const float* __restrict__ col,
                       const float* __restrict__ vg, float* __restrict__ xout,
                       hf* __restrict__ oh) {
    int blk = blockIdx.x;
    int p = blk % NPOS, b = blk / NPOS;
    int i = p / WO, j = p % WO;
    int t = threadIdx.x;
    __shared__ float wgt[4][9];
    __shared__ int npos[9];
    if (t < 9) {
        int a = t/3, c = t%3;
        int ni = min(max(i-1,0),25)+a, nj = min(max(j-1,0),25)+c;
        npos[t] = ni*WO + nj;
    }
    __syncthreads();
    if (t < 36) {
        int n = t/9, ac = t%9;
        float av = attn[((size_t)(b*4+n)*NPOS + p)*9 + ac];
        wgt[n][ac] = av / (col[b*NPOS + npos[ac]] + 1e-8f);
    }
    __syncthreads();
    float acc = xout[(size_t)blk*DD + t];
    #pragma unroll
    for (int n=0;n<4;n++) {
        const float* vb = vg + (size_t)(b*4+n)*NPOS*DD;
        #pragma unroll
        for (int ac=0;ac<9;ac++)
            acc = fmaf(wgt[n][ac], vb[(size_t)npos[ac]*DD + t], acc);
    }
    xout[(size_t)blk*DD + t] = acc;
    oh[(size_t)blk*DD + t] = __float2half(acc);
}

// ---------------- RoPE table ----------------
__global__ void rope_tab(float* __restrict__ cs, float* __restrict__ sn) {
    int idx = blockIdx.x*blockDim.x + threadIdx.x;
    if (idx >= NPOS*16) return;
    int pos = idx / 16, r = idx % 16;
    float f = expf(-((float)(2*r) / 32.f) * 9.210340371976184f);
    float ang = (float)pos * f;
    cs[idx] = cosf(ang);
    sn[idx] = sinf(ang);
}

// ---------------- block NA (K=7): row-blocked, smem-staged k/v window ----------------
#define NA7_SMEM ((2*6272 + 8*64) * 4)
__global__ void __launch_bounds__(256)
na7_row(const float* __restrict__ qkv, hf* __restrict__ oh) {
    extern __shared__ float sm7[];
    float* ks = sm7;
    float* vs = sm7 + 6272;
    float* wb = sm7 + 12544;
    int blk = blockIdx.x;
    int i = blk % 28; int bh = blk / 28; int h = bh & 7; int b = bh >> 3;
    int t = threadIdx.x, w = t >> 5, lane = t & 31;
    int si = min(max(i-3,0),21);
    for (int idx = t; idx < 1568; idx += 256) {
        int pos = idx >> 3, f = (idx & 7) * 4;
        int a = pos / 28, c = pos % 28;
        size_t g = ((size_t)(b*NPOS + (si+a)*WO + c))*768 + h*32 + f;
        *(float4*)(ks + pos*32 + f) = *(const float4*)(qkv + g + 256);
        *(float4*)(vs + pos*32 + f) = *(const float4*)(qkv + g + 512);
    }
    __syncthreads();
    for (int j = w; j < 28; j += 8) {
        int sj = min(max(j-3,0),21);
        int p = i*WO + j;
        float qd = qkv[((size_t)(b*NPOS + p))*768 + h*32 + lane];
        for (int nb = 0; nb < 49; nb++) {
            int a = nb / 7, c = nb % 7;
            float s = qd * ks[(a*28 + sj + c)*32 + lane];
            #pragma unroll
            for (int o=16;o;o>>=1) s += __shfl_xor_sync(0xffffffffu, s, o);
            if (lane == 0) wb[w*64 + nb] = s * 0.17677669529663687f;
        }
        __syncwarp();
        float m = -1e30f;
        for (int nb = lane; nb < 49; nb += 32) m = fmaxf(m, wb[w*64 + nb]);
        #pragma unroll
        for (int o=16;o;o>>=1) m = fmaxf(m, __shfl_xor_sync(0xffffffffu, m, o));
        float sum = 0.f;
        for (int nb = lane; nb < 49; nb += 32) {
            float e = expf(wb[w*64 + nb] - m);
            wb[w*64 + nb] = e;
            sum += e;
        }
        #pragma unroll
        for (int o=16;o;o>>=1) sum += __shfl_xor_sync(0xffffffffu, sum, o);
        __syncwarp();
        float inv = 1.f / sum;
        float acc = 0.f;
        for (int nb = 0; nb < 49; nb++) {
            int a = nb / 7, c = nb % 7;
            acc = fmaf(wb[w*64 + nb] * inv, vs[(a*28 + sj + c)*32 + lane], acc);
        }
        size_t o = ((size_t)(b*NPOS + p))*DD + h*32 + lane;
        oh[o] = __float2half(acc);
        __syncwarp();
    }
}

// ---------------- host helpers ----------------
static inline void run_tc(const hf* Ah, const hf* Bh, const hf* Bl,
                          const float* bias, float* C, hf* Oh,
                          const float* cs, const float* sn,
                          int Mreal, int Mpad, int N, int K, int act, int remap, int ks) {
    dim3 grid(N/64, Mpad/64, ks);
    gemm_mma<<<grid, 256, GTC_SMEM>>>(Ah, Bh, Bl, bias, C, Oh, cs, sn,
                                      Mreal, Mpad, N, K, act, remap, ks);
}

extern "C" void kernel_launch(void* const* d_in, const int* in_sizes, int n_in,
                              void* d_out, int out_size) {
    const float* x          = (const float*)d_in[0];
    const float* g_seed_w   = (const float*)d_in[1];
    const float* g_q_w      = (const float*)d_in[2];
    const float* g_k_w      = (const float*)d_in[3];
    const float* g_v_w      = (const float*)d_in[4];
    const float* g_mlp_w1   = (const float*)d_in[5];
    const float* g_mlp_b1   = (const float*)d_in[6];
    const float* g_mlp_w2   = (const float*)d_in[7];
    const float* g_mlp_b2   = (const float*)d_in[8];
    const float* g_ln_in_g  = (const float*)d_in[9];
    const float* g_ln_in_b  = (const float*)d_in[10];
    const float* g_ln_out_g = (const float*)d_in[11];
    const float* g_ln_out_b = (const float*)d_in[12];
    const float* g_tau      = (const float*)d_in[13];
    const float* g_rpb      = (const float*)d_in[14];
    const float* blk_ln1_g  = (const float*)d_in[15];
    const float* blk_ln1_b  = (const float*)d_in[16];
    const float* blk_qkv_w  = (const float*)d_in[17];
    const float* blk_proj_w = (const float*)d_in[18];
    const float* blk_proj_b = (const float*)d_in[19];
    const float* blk_ln2_g  = (const float*)d_in[20];
    const float* blk_ln2_b  = (const float*)d_in[21];
    const float* blk_mlp_w1 = (const float*)d_in[22];
    const float* blk_mlp_b1 = (const float*)d_in[23];
    const float* blk_mlp_w2 = (const float*)d_in[24];
    const float* blk_mlp_b2 = (const float*)d_in[25];
    float* out = (float*)d_out;

    cudaFuncSetAttribute(gemm_mma, cudaFuncAttributeMaxDynamicSharedMemorySize, GTC_SMEM);
    cudaFuncSetAttribute(na7_row, cudaFuncAttributeMaxDynamicSharedMemorySize, NA7_SMEM);

#define SYM(v, s) cudaGetSymbolAddress((void**)&v, s)
    float *xout, *buf2, *kg, *vg, *split, *attn, *colsum, *csb, *snb;
    SYM(xout,g_xout); SYM(buf2,g_buf2);
    SYM(kg,g_kg); SYM(vg,g_vg); SYM(split,g_split); SYM(attn,g_attn);
    SYM(colsum,g_colsum); SYM(csb,g_cos); SYM(snb,g_sin);
    hf *xh,*lnxh,*colh,*a1h,*a2h;
    SYM(xh,g_xh); SYM(lnxh,g_lnxh); SYM(colh,g_colh);
    SYM(a1h,g_a1h); SYM(a2h,g_a2h);
    hf *wsh,*wsl,*wqh,*wql,*wkh,*wkl,*wvh,*wvl,*m1h,*m1l,*m2h,*m2l;
    SYM(wsh,g_wsh); SYM(wsl,g_wsl); SYM(wqh,g_wqh); SYM(wql,g_wql);
    SYM(wkh,g_wkh); SYM(wkl,g_wkl); SYM(wvh,g_wvh); SYM(wvl,g_wvl);
    SYM(m1h,g_m1h); SYM(m1l,g_m1l); SYM(m2h,g_m2h); SYM(m2l,g_m2l);
    hf *qkvh,*qkvl,*pjh,*pjl,*bm1h,*bm1l,*bm2h,*bm2l;
    SYM(qkvh,g_qkvh); SYM(qkvl,g_qkvl); SYM(pjh,g_pjh); SYM(pjl,g_pjl);
    SYM(bm1h,g_bm1h); SYM(bm1l,g_bm1l); SYM(bm2h,g_bm2h); SYM(bm2l,g_bm2l);
#undef SYM

    // ---- weight conversions ----
    wseed_tr_hl<<<(DD*2304 + 255)/256, 256>>>(g_seed_w, wsh, wsl);
    {
        CvtSegs cs;
        cs.src[0]=g_q_w;      cs.hi[0]=wqh;  cs.lo[0]=wql;
        cs.src[1]=g_k_w;      cs.hi[1]=wkh;  cs.lo[1]=wkl;
        cs.src[2]=g_v_w;      cs.hi[2]=wvh;  cs.lo[2]=wvl;
        cs.src[3]=g_mlp_w1;   cs.hi[3]=m1h;  cs.lo[3]=m1l;
        cs.src[4]=g_mlp_w2;   cs.hi[4]=m2h;  cs.lo[4]=m2l;
        cs.src[5]=blk_qkv_w;  cs.hi[5]=qkvh; cs.lo[5]=qkvl;
        cs.src[6]=blk_proj_w; cs.hi[6]=pjh;  cs.lo[6]=pjl;
        cs.src[7]=blk_mlp_w1; cs.hi[7]=bm1h; cs.lo[7]=bm1l;
        cs.src[8]=blk_mlp_w2; cs.hi[8]=bm2h; cs.lo[8]=bm2l;
        cvt_all<<<(CVT_TOT + 255)/256, 256>>>(cs);
    }

    // ---- LN_in(x) + raw x fp16 in one pass ----
    ln_warp<<<(NTOKIN + 7)/8, 256>>>(x, g_ln_in_g, g_ln_in_b, lnxh, xh, NTOKIN);
    run_tc(lnxh, wkh, wkl, nullptr, kg, nullptr, nullptr, nullptr,
           NTOKIN, NTOKIN, DD, DD, 0, 1, 1);
    run_tc(xh,   wvh, wvl, nullptr, vg, nullptr, nullptr, nullptr,
           NTOKIN, NTOKIN, DD, DD, 0, 1, 1);

    // ---- seed conv ----
    im2col_h<<<(NTOK*576 + 255)/256, 256>>>(x, colh);
    run_tc(colh, wsh, wsl, nullptr, split, nullptr, nullptr, nullptr,
           NTOK, NTOKP, DD, 2304, 0, 0, 3);
    combine_ln2<<<(NTOK + 7)/8, 256>>>(split, 3, nullptr, g_ln_out_g, g_ln_out_b,
                                       nullptr, xout, g_ln_out_g, g_ln_out_b,
                                       a2h, NTOKP, NTOK);

    rope_tab<<<(NPOS*16 + 255)/256, 256>>>(csb, snb);

    // ---- 3 grouped-NA seeding iterations ----
    for (int it = 0; it < 3; it++) {
        run_tc(a2h, wqh, wql, nullptr, split, nullptr, nullptr, nullptr,
               NTOK, NTOKP, DD, DD, 0, 0, 2);
        na3_attn4<<<NTOK, 288>>>(kg, split, g_rpb, g_tau, attn);
        col_sum_k<<<(BB*NPOS + 255)/256, 256>>>(attn, colsum);
        na3_av<<<NTOK, 256>>>(attn, colsum, vg, xout, a2h);
        run_tc(a2h, m1h, m1l, g_mlp_b1, nullptr, a1h, nullptr, nullptr,
               NTOK, NTOKP, 512, DD, 1, 0, 1);
        run_tc(a1h, m2h, m2l, nullptr, split, nullptr, nullptr, nullptr,
               NTOK, NTOKP, DD, 512, 0, 0, 2);
        const float* g2 = (it < 2) ? g_ln_out_g : blk_ln1_g;
        const float* b2 = (it < 2) ? g_ln_out_b : blk_ln1_b;
        combine_ln2<<<(NTOK + 7)/8, 256>>>(split, 2, g_mlp_b2, g_ln_out_g, g_ln_out_b,
                                           xout, xout, g2, b2, a2h, NTOKP, NTOK);
    }

    // ---- 2 transformer blocks with 7x7 NA ----
    for (int l = 0; l < 2; l++) {
        run_tc(a2h, qkvh + (size_t)l*768*DD, qkvl + (size_t)l*768*DD,
               nullptr, buf2, nullptr, csb, snb,
               NTOK, NTOKP, 768, DD, 0, 0, 1);
        na7_row<<<BB*HEADS*28, 256, NA7_SMEM>>>(buf2, a2h);
        run_tc(a2h, pjh + (size_t)l*DD*DD, pjl + (size_t)l*DD*DD,
               nullptr, split, nullptr, nullptr, nullptr,
               NTOK, NTOKP, DD, DD, 0, 0, 2);
        combine_res_ln<<<(NTOK + 7)/8, 256>>>(split, 2, blk_proj_b + l*DD, xout, xout,
                                              blk_ln2_g + l*DD, blk_ln2_b + l*DD,
                                              a2h, NTOKP, NTOK);
        run_tc(a2h, bm1h + (size_t)l*768*DD, bm1l + (size_t)l*768*DD,
               blk_mlp_b1 + l*768, nullptr, a1h, nullptr, nullptr,
               NTOK, NTOKP, 768, DD, 1, 0, 1);
        run_tc(a1h, bm2h + (size_t)l*DD*768, bm2l + (size_t)l*DD*768,
               nullptr, split, nullptr, nullptr, nullptr,
               NTOK, NTOKP, DD, 768, 0, 0, 2);
        if (l == 0) {
            combine_res_ln<<<(NTOK + 7)/8, 256>>>(split, 2, blk_mlp_b2, xout, xout,
                                                  blk_ln1_g + DD, blk_ln1_b + DD,
                                                  a2h, NTOKP, NTOK);
        } else {
            int tot4 = (NTOK*DD) >> 2;
            combine_k<<<(tot4 + 255)/256, 256>>>(split, 2, blk_mlp_b2 + DD, xout, out,
                                                 NTOK, NTOKP, DD, 0);
        }
    }
}

// round 16
// speedup vs baseline: 1.1683x; 1.0035x over previous
#include <cuda_runtime.h>
#include <cuda_fp16.h>
#include <math.h>
#include <stdint.h>

// ---------------- problem constants ----------------
#define BB 4
#define HI 56
#define WI 56
#define DD 256
#define HO 28
#define WO 28
#define NPOS 784
#define NTOK (BB*NPOS)     // 3136
#define NTOKP 3200
#define NTOKIN (BB*HI*WI)  // 12544
#define HEADS 8
#define LN_EPS 1e-5f

typedef __half hf;

// ---------------- scratch (device globals) ----------------
__device__ float g_xout  [NTOK*DD];
__device__ float g_buf2  [NTOK*768];
__device__ float g_kg    [BB*4*NPOS*DD];
__device__ float g_vg    [BB*4*NPOS*DD];
__device__ float g_split [3*NTOKP*DD];
__device__ float g_attn  [BB*4*NPOS*9];
__device__ float g_colsum[BB*NPOS];
__device__ float g_cos   [NPOS*16];
__device__ float g_sin   [NPOS*16];

__device__ hf g_xh[NTOKIN*DD];
__device__ hf g_lnxh[NTOKIN*DD];
__device__ hf g_colh[NTOKP*2304];
__device__ hf g_a1h[NTOKP*768];
__device__ hf g_a2h[NTOKP*256];
__device__ hf g_wsh[DD*2304], g_wsl[DD*2304];
__device__ hf g_wqh[DD*DD],   g_wql[DD*DD];
__device__ hf g_wkh[DD*DD],   g_wkl[DD*DD];
__device__ hf g_wvh[DD*DD],   g_wvl[DD*DD];
__device__ hf g_m1h[512*DD],  g_m1l[512*DD];
__device__ hf g_m2h[DD*512],  g_m2l[DD*512];
__device__ hf g_qkvh[2*768*DD], g_qkvl[2*768*DD];
__device__ hf g_pjh[2*DD*DD],   g_pjl[2*DD*DD];
__device__ hf g_bm1h[2*768*DD], g_bm1l[2*768*DD];
__device__ hf g_bm2h[2*DD*768], g_bm2l[2*DD*768];

// ---------------- helpers ----------------
__device__ __forceinline__ uint32_t smem_u32(const void* p) {
    uint32_t a;
    asm("{ .reg .u64 t; cvta.to.shared.u64 t, %1; cvt.u32.u64 %0, t; }" : "=r"(a) : "l"(p));
    return a;
}
__device__ __forceinline__ float gelu_exact(float x) {
    return 0.5f * x * (1.f + erff(x * 0.70710678118654752f));
}
__device__ __forceinline__ void cp16(uint32_t saddr, const void* gaddr) {
    asm volatile("cp.async.cg.shared.global [%0], [%1], 16;" :: "r"(saddr), "l"(gaddr));
}
#define CP_COMMIT() asm volatile("cp.async.commit_group;" ::: "memory")
#define CP_WAIT0()  asm volatile("cp.async.wait_group 0;" ::: "memory")

__device__ __forceinline__ void ldmx4(uint32_t addr, uint32_t* r) {
    asm volatile("ldmatrix.sync.aligned.m8n8.x4.shared.b16 {%0,%1,%2,%3}, [%4];"
        : "=r"(r[0]), "=r"(r[1]), "=r"(r[2]), "=r"(r[3]) : "r"(addr));
}
__device__ __forceinline__ void mma16816(float* d, const uint32_t* a, uint32_t b0, uint32_t b1) {
    asm volatile("mma.sync.aligned.m16n8k16.row.col.f32.f16.f16.f32 "
        "{%0,%1,%2,%3}, {%4,%5,%6,%7}, {%8,%9}, {%0,%1,%2,%3};"
        : "+f"(d[0]), "+f"(d[1]), "+f"(d[2]), "+f"(d[3])
        : "r"(a[0]), "r"(a[1]), "r"(a[2]), "r"(a[3]), "r"(b0), "r"(b1));
}
__device__ __forceinline__ void split_hl(float v, hf& h, hf& l) {
    h = __float2half(v);
    l = __float2half(v - __half2float(h));
}

// ---------------- tensor-core GEMM (mma.sync fp16, 2-pass), M-tile templated ----------------
#define TROW 144
#define BTSZ (64*TROW)          // 9216 (B tiles are always 64 rows)

template<int BM>
__global__ void __launch_bounds__(256, (BM == 64 ? 4 : 3))
gemm_mma(const hf* __restrict__ Ah, const hf* __restrict__ Bh, const hf* __restrict__ Bl,
         const float* __restrict__ bias, float* __restrict__ C,
         hf* __restrict__ Oh,
         const float* __restrict__ CS, const float* __restrict__ SN,
         int Mreal, int Mpad, int N, int K, int act, int remap, int ksplit) {
    constexpr int ATSZ = BM * TROW;
    constexpr int BUFSZ = ATSZ + 2*BTSZ;
    constexpr int MI = BM / 32;           // m-fragments per warp
    extern __shared__ char smraw[];
    uint32_t sb = smem_u32(smraw);
    int tid = threadIdx.x, wid = tid >> 5, lane = tid & 31;
    int wm = wid >> 2, wn = wid & 3;      // 2 x 4 warps; warp tile (BM/2) x 16
    int bm = blockIdx.y * BM, bn = blockIdx.x * 64;
    int kper = K / ksplit;
    int kbase = blockIdx.z * kper;
    int nch = kper / 64;

    const hf* srcA = Ah + (size_t)bm*K;
    const hf* srcB[2] = { Bh + (size_t)bn*K, Bl + (size_t)bn*K };

    #define LOAD_CHUNK(c, b) {                                                  \
        int k0 = kbase + (c)*64;                                                \
        uint32_t dbase = sb + (b)*BUFSZ;                                        \
        _Pragma("unroll")                                                       \
        for (int u = 0; u < BM/32; u++) {                                       \
            int idx = tid + u*256;                                              \
            int row = idx >> 3, seg = idx & 7;                                  \
            cp16(dbase + row*TROW + seg*16,                                     \
                 srcA + (size_t)row*K + k0 + seg*8);                            \
        }                                                                       \
        _Pragma("unroll")                                                       \
        for (int s = 0; s < 2; s++) {                                           \
            uint32_t dst = dbase + ATSZ + s*BTSZ;                               \
            _Pragma("unroll")                                                   \
            for (int u = 0; u < 2; u++) {                                       \
                int idx = tid + u*256;                                          \
                int brow = idx >> 3, bseg = idx & 7;                            \
                cp16(dst + brow*TROW + bseg*16,                                 \
                     srcB[s] + (size_t)brow*K + k0 + bseg*8);                   \
            }                                                                   \
        }                                                                       \
        CP_COMMIT();                                                            \
    }

    float acc[MI][2][4];
    #pragma unroll
    for (int i=0;i<MI;i++)
        #pragma unroll
        for (int j=0;j<2;j++)
            #pragma unroll
            for (int e=0;e<4;e++) acc[i][j][e] = 0.f;

    LOAD_CHUNK(0, 0)
    int buf = 0;
    int lr16 = lane & 15, lh = lane >> 4;

    for (int c = 0; c < nch; c++) {
        CP_WAIT0();
        __syncthreads();
        if (c + 1 < nch) LOAD_CHUNK(c+1, buf^1)
        uint32_t aA = sb + buf*BUFSZ;
        uint32_t bH = aA + ATSZ;
        uint32_t bL = aA + 2*ATSZ - ATSZ + BTSZ;   // = aA + ATSZ + BTSZ
        #pragma unroll
        for (int kk = 0; kk < 4; kk++) {
            uint32_t ah[MI][4], bh[4], bl[4];
            int kb = kk*32 + lh*16;
            #pragma unroll
            for (int mi = 0; mi < MI; mi++) {
                int row = wm*(BM/2) + mi*16 + lr16;
                ldmx4(aA + row*TROW + kb, ah[mi]);
            }
            {
                int row = wn*16 + lr16;
                ldmx4(bH + row*TROW + kb, bh);
                ldmx4(bL + row*TROW + kb, bl);
            }
            #pragma unroll
            for (int mi = 0; mi < MI; mi++) {
                #pragma unroll
                for (int nj = 0; nj < 2; nj++) {
                    mma16816(acc[mi][nj], ah[mi], bh[nj], bh[nj+2]);
                    mma16816(acc[mi][nj], ah[mi], bl[nj], bl[nj+2]);
                }
            }
        }
        __syncthreads();
        buf ^= 1;
    }
    #undef LOAD_CHUNK

    int cbase = bn + wn*16 + (lane & 3)*2;
    int rbase = bm + wm*(BM/2) + (lane >> 2);
    if (ksplit > 1) {
        float* Cp = C + (size_t)blockIdx.z * Mpad * N;
        #pragma unroll
        for (int mi = 0; mi < MI; mi++) {
            #pragma unroll
            for (int half = 0; half < 2; half++) {
                int r = rbase + mi*16 + half*8;
                if (r >= Mreal) continue;
                #pragma unroll
                for (int nj = 0; nj < 2; nj++) {
                    float2 v = make_float2(acc[mi][nj][half*2], acc[mi][nj][half*2+1]);
                    *(float2*)(Cp + (size_t)r*N + cbase + nj*8) = v;
                }
            }
        }
        return;
    }
    #pragma unroll
    for (int mi = 0; mi < MI; mi++) {
        #pragma unroll
        for (int half = 0; half < 2; half++) {
            int r = rbase + mi*16 + half*8;
            if (r >= Mreal) continue;
            int orow = r;
            if (remap) {
                int b2 = r / (HI*WI); int rr = r % (HI*WI);
                int hi2 = rr / WI, wi2 = rr % WI;
                orow = (b2*4 + (hi2&1)*2 + (wi2&1))*NPOS + (hi2>>1)*WO + (wi2>>1);
            }
            #pragma unroll
            for (int nj = 0; nj < 2; nj++) {
                int col = cbase + nj*8;
                float v0 = acc[mi][nj][half*2], v1 = acc[mi][nj][half*2+1];
                if (bias) { v0 += bias[col]; v1 += bias[col+1]; }
                if (act)  { v0 = gelu_exact(v0); v1 = gelu_exact(v1); }
                if (CS && col < 512) {
                    int pos = orow % NPOS;
                    int rr2 = (col & 31) >> 1;
                    float c = CS[pos*16 + rr2], s = SN[pos*16 + rr2];
                    float t0 = v0*c - v1*s;
                    v1 = v1*c + v0*s;
                    v0 = t0;
                }
                if (Oh) {
                    __half2 hv;
                    hv.x = __float2half(v0);
                    hv.y = __float2half(v1);
                    *(__half2*)(Oh + (size_t)orow*N + col) = hv;
                } else {
                    *(float2*)(C + (size_t)orow*N + col) = make_float2(v0, v1);
                }
            }
        }
    }
}

#define GTC_SMEM64  (2*(64*TROW  + 2*BTSZ))   // 55296
#define GTC_SMEM128 (2*(128*TROW + 2*BTSZ))   // 73728

// ---------------- merged weight converter (9 segments) ----------------
struct CvtSegs {
    const float* src[9];
    hf* hi[9];
    hf* lo[9];
};
#define S0 16384
#define S1 16384
#define S2 16384
#define S3 32768
#define S4 32768
#define S5 98304
#define S6 32768
#define S7 98304
#define S8 98304
#define CVT_TOT (S0+S1+S2+S3+S4+S5+S6+S7+S8)

__global__ void cvt_all(CvtSegs segs) {
    int i = blockIdx.x*blockDim.x + threadIdx.x;
    if (i >= CVT_TOT) return;
    int seg, off = i;
    if      (off < S0) seg = 0;
    else if ((off -= S0) < S1) seg = 1;
    else if ((off -= S1) < S2) seg = 2;
    else if ((off -= S2) < S3) seg = 3;
    else if ((off -= S3) < S4) seg = 4;
    else if ((off -= S4) < S5) seg = 5;
    else if ((off -= S5) < S6) seg = 6;
    else if ((off -= S6) < S7) seg = 7;
    else { off -= S7; seg = 8; }
    float4 v = ((const float4*)segs.src[seg])[off];
    __half2 h0, h1, l0, l1;
    split_hl(v.x, h0.x, l0.x); split_hl(v.y, h0.y, l0.y);
    split_hl(v.z, h1.x, l1.x); split_hl(v.w, h1.y, l1.y);
    ((__half2*)segs.hi[seg])[2*off]   = h0;
    ((__half2*)segs.hi[seg])[2*off+1] = h1;
    ((__half2*)segs.lo[seg])[2*off]   = l0;
    ((__half2*)segs.lo[seg])[2*off+1] = l1;
}

// ---------------- warp-per-row LN over 256 (+ optional raw fp16 out) ----------------
__global__ void ln_warp(const float* __restrict__ in, const float* __restrict__ gamma,
                        const float* __restrict__ beta,
                        hf* __restrict__ oh, hf* __restrict__ rh, int nrows) {
    int gw = (blockIdx.x * blockDim.x + threadIdx.x) >> 5;
    int lane = threadIdx.x & 31;
    if (gw >= nrows) return;
    const float4* row = (const float4*)(in + (size_t)gw * DD);
    float4 v0 = row[lane], v1 = row[lane + 32];
    if (rh) {
        __half2* hp = (__half2*)(rh + (size_t)gw * DD);
        __half2 h0, h1;
        h0.x = __float2half(v0.x); h0.y = __float2half(v0.y);
        h1.x = __float2half(v0.z); h1.y = __float2half(v0.w);
        hp[lane*2] = h0; hp[lane*2+1] = h1;
        h0.x = __float2half(v1.x); h0.y = __float2half(v1.y);
        h1.x = __float2half(v1.z); h1.y = __float2half(v1.w);
        hp[64+lane*2] = h0; hp[64+lane*2+1] = h1;
    }
    float s = v0.x+v0.y+v0.z+v0.w + v1.x+v1.y+v1.z+v1.w;
    #pragma unroll
    for (int o=16;o;o>>=1) s += __shfl_xor_sync(0xffffffffu, s, o);
    float mean = s * (1.f/256.f);
    float d[8] = {v0.x-mean, v0.y-mean, v0.z-mean, v0.w-mean,
                  v1.x-mean, v1.y-mean, v1.z-mean, v1.w-mean};
    float sq = 0.f;
    #pragma unroll
    for (int e=0;e<8;e++) sq += d[e]*d[e];
    #pragma unroll
    for (int o=16;o;o>>=1) sq += __shfl_xor_sync(0xffffffffu, sq, o);
    float inv = rsqrtf(sq * (1.f/256.f) + LN_EPS);
    float4 g0 = ((const float4*)gamma)[lane], g1 = ((const float4*)gamma)[lane+32];
    float4 b0 = ((const float4*)beta)[lane],  b1 = ((const float4*)beta)[lane+32];
    float y[8];
    y[0]=d[0]*inv*g0.x+b0.x; y[1]=d[1]*inv*g0.y+b0.y; y[2]=d[2]*inv*g0.z+b0.z; y[3]=d[3]*inv*g0.w+b0.w;
    y[4]=d[4]*inv*g1.x+b1.x; y[5]=d[5]*inv*g1.y+b1.y; y[6]=d[6]*inv*g1.z+b1.z; y[7]=d[7]*inv*g1.w+b1.w;
    __half2* hp = (__half2*)(oh + (size_t)gw * DD);
    #pragma unroll
    for (int q = 0; q < 4; q++) {
        __half2 hv;
        hv.x = __float2half(y[q*2]);
        hv.y = __float2half(y[q*2+1]);
        int idx = (q < 2) ? (lane*2 + q) : (64 + lane*2 + (q-2));
        hp[idx] = hv;
    }
}

// warp-level LN of an 8-element-per-lane fragment, then fp16 store
__device__ __forceinline__ void ln_store_h(float* y, const float* gamma, const float* beta,
                                           int lane, hf* oh, size_t rowoff) {
    float sm = 0.f;
    #pragma unroll
    for (int e=0;e<8;e++) sm += y[e];
    #pragma unroll
    for (int o=16;o;o>>=1) sm += __shfl_xor_sync(0xffffffffu, sm, o);
    float mean = sm * (1.f/256.f);
    float d[8], sq = 0.f;
    #pragma unroll
    for (int e=0;e<8;e++) { d[e] = y[e]-mean; sq += d[e]*d[e]; }
    #pragma unroll
    for (int o=16;o;o>>=1) sq += __shfl_xor_sync(0xffffffffu, sq, o);
    float inv = rsqrtf(sq * (1.f/256.f) + LN_EPS);
    float4 g0 = ((const float4*)gamma)[lane], g1 = ((const float4*)gamma)[lane+32];
    float4 b0 = ((const float4*)beta)[lane],  b1 = ((const float4*)beta)[lane+32];
    float z[8];
    z[0]=d[0]*inv*g0.x+b0.x; z[1]=d[1]*inv*g0.y+b0.y; z[2]=d[2]*inv*g0.z+b0.z; z[3]=d[3]*inv*g0.w+b0.w;
    z[4]=d[4]*inv*g1.x+b1.x; z[5]=d[5]*inv*g1.y+b1.y; z[6]=d[6]*inv*g1.z+b1.z; z[7]=d[7]*inv*g1.w+b1.w;
    __half2* hp = (__half2*)(oh + rowoff);
    #pragma unroll
    for (int q = 0; q < 4; q++) {
        __half2 hv;
        hv.x = __float2half(z[q*2]);
        hv.y = __float2half(z[q*2+1]);
        int idx = (q < 2) ? (lane*2 + q) : (64 + lane*2 + (q-2));
        hp[idx] = hv;
    }
}

// ---------------- combine(+bias) -> LN1 -> +res -> xout; then LN2 -> fp16 ----------------
__global__ void combine_ln2(const float* __restrict__ part, int s,
                            const float* __restrict__ bias,
                            const float* __restrict__ g1, const float* __restrict__ b1,
                            const float* __restrict__ res, float* __restrict__ outf,
                            const float* __restrict__ g2, const float* __restrict__ b2,
                            hf* __restrict__ oh, int Mpad, int nrows) {
    int gw = (blockIdx.x * blockDim.x + threadIdx.x) >> 5;
    int lane = threadIdx.x & 31;
    if (gw >= nrows) return;
    float y[8];
    {
        const float4* p0 = (const float4*)(part + (size_t)gw * DD);
        float4 v0 = p0[lane], v1 = p0[lane+32];
        y[0]=v0.x; y[1]=v0.y; y[2]=v0.z; y[3]=v0.w;
        y[4]=v1.x; y[5]=v1.y; y[6]=v1.z; y[7]=v1.w;
        for (int z = 1; z < s; z++) {
            const float4* pz = (const float4*)(part + (size_t)z*Mpad*DD + (size_t)gw * DD);
            float4 w0 = pz[lane], w1 = pz[lane+32];
            y[0]+=w0.x; y[1]+=w0.y; y[2]+=w0.z; y[3]+=w0.w;
            y[4]+=w1.x; y[5]+=w1.y; y[6]+=w1.z; y[7]+=w1.w;
        }
    }
    if (bias) {
        float4 c0 = ((const float4*)bias)[lane], c1 = ((const float4*)bias)[lane+32];
        y[0]+=c0.x; y[1]+=c0.y; y[2]+=c0.z; y[3]+=c0.w;
        y[4]+=c1.x; y[5]+=c1.y; y[6]+=c1.z; y[7]+=c1.w;
    }
    float sm = 0.f;
    #pragma unroll
    for (int e=0;e<8;e++) sm += y[e];
    #pragma unroll
    for (int o=16;o;o>>=1) sm += __shfl_xor_sync(0xffffffffu, sm, o);
    float mean = sm * (1.f/256.f);
    float sq = 0.f;
    #pragma unroll
    for (int e=0;e<8;e++) { y[e] -= mean; sq += y[e]*y[e]; }
    #pragma unroll
    for (int o=16;o;o>>=1) sq += __shfl_xor_sync(0xffffffffu, sq, o);
    float inv = rsqrtf(sq * (1.f/256.f) + LN_EPS);
    float4 gg0 = ((const float4*)g1)[lane], gg1 = ((const float4*)g1)[lane+32];
    float4 bb0 = ((const float4*)b1)[lane], bb1 = ((const float4*)b1)[lane+32];
    y[0]=y[0]*inv*gg0.x+bb0.x; y[1]=y[1]*inv*gg0.y+bb0.y; y[2]=y[2]*inv*gg0.z+bb0.z; y[3]=y[3]*inv*gg0.w+bb0.w;
    y[4]=y[4]*inv*gg1.x+bb1.x; y[5]=y[5]*inv*gg1.y+bb1.y; y[6]=y[6]*inv*gg1.z+bb1.z; y[7]=y[7]*inv*gg1.w+bb1.w;
    if (res) {
        const float4* rr = (const float4*)(res + (size_t)gw * DD);
        float4 r0 = rr[lane], r1 = rr[lane+32];
        y[0]+=r0.x; y[1]+=r0.y; y[2]+=r0.z; y[3]+=r0.w;
        y[4]+=r1.x; y[5]+=r1.y; y[6]+=r1.z; y[7]+=r1.w;
    }
    float4* op = (float4*)(outf + (size_t)gw * DD);
    op[lane]    = make_float4(y[0],y[1],y[2],y[3]);
    op[lane+32] = make_float4(y[4],y[5],y[6],y[7]);
    ln_store_h(y, g2, b2, lane, oh, (size_t)gw * DD);
}

// ---------------- combine(+bias) -> +res -> xout; then LN -> fp16 ----------------
__global__ void combine_res_ln(const float* __restrict__ part, int s,
                               const float* __restrict__ bias, const float* __restrict__ res,
                               float* __restrict__ outf,
                               const float* __restrict__ g2, const float* __restrict__ b2,
                               hf* __restrict__ oh, int Mpad, int nrows) {
    int gw = (blockIdx.x * blockDim.x + threadIdx.x) >> 5;
    int lane = threadIdx.x & 31;
    if (gw >= nrows) return;
    float y[8];
    {
        const float4* p0 = (const float4*)(part + (size_t)gw * DD);
        float4 v0 = p0[lane], v1 = p0[lane+32];
        y[0]=v0.x; y[1]=v0.y; y[2]=v0.z; y[3]=v0.w;
        y[4]=v1.x; y[5]=v1.y; y[6]=v1.z; y[7]=v1.w;
        for (int z = 1; z < s; z++) {
            const float4* pz = (const float4*)(part + (size_t)z*Mpad*DD + (size_t)gw * DD);
            float4 w0 = pz[lane], w1 = pz[lane+32];
            y[0]+=w0.x; y[1]+=w0.y; y[2]+=w0.z; y[3]+=w0.w;
            y[4]+=w1.x; y[5]+=w1.y; y[6]+=w1.z; y[7]+=w1.w;
        }
    }
    if (bias) {
        float4 c0 = ((const float4*)bias)[lane], c1 = ((const float4*)bias)[lane+32];
        y[0]+=c0.x; y[1]+=c0.y; y[2]+=c0.z; y[3]+=c0.w;
        y[4]+=c1.x; y[5]+=c1.y; y[6]+=c1.z; y[7]+=c1.w;
    }
    {
        const float4* rr = (const float4*)(res + (size_t)gw * DD);
        float4 r0 = rr[lane], r1 = rr[lane+32];
        y[0]+=r0.x; y[1]+=r0.y; y[2]+=r0.z; y[3]+=r0.w;
        y[4]+=r1.x; y[5]+=r1.y; y[6]+=r1.z; y[7]+=r1.w;
    }
    float4* op = (float4*)(outf + (size_t)gw * DD);
    op[lane]    = make_float4(y[0],y[1],y[2],y[3]);
    op[lane+32] = make_float4(y[4],y[5],y[6],y[7]);
    ln_store_h(y, g2, b2, lane, oh, (size_t)gw * DD);
}

// ---------------- plain split-K combine with epilogue ----------------
__global__ void combine_k(const float* __restrict__ part, int s,
                          const float* __restrict__ bias, const float* __restrict__ res,
                          float* __restrict__ out, int Mreal, int Mpad, int N, int act) {
    int i4 = blockIdx.x*blockDim.x + threadIdx.x;
    int tot = (Mreal*N) >> 2;
    if (i4 >= tot) return;
    size_t zs = ((size_t)Mpad*N) >> 2;
    float4 v = ((const float4*)part)[i4];
    for (int z = 1; z < s; z++) {
        float4 w = ((const float4*)part)[i4 + z*zs];
        v.x+=w.x; v.y+=w.y; v.z+=w.z; v.w+=w.w;
    }
    int col = (i4*4) % N;
    if (bias) {
        float4 bvv = *(const float4*)(bias + col);
        v.x+=bvv.x; v.y+=bvv.y; v.z+=bvv.z; v.w+=bvv.w;
    }
    if (act) { v.x=gelu_exact(v.x); v.y=gelu_exact(v.y); v.z=gelu_exact(v.z); v.w=gelu_exact(v.w); }
    if (res) {
        float4 rr = ((const float4*)res)[i4];
        v.x+=rr.x; v.y+=rr.y; v.z+=rr.z; v.w+=rr.w;
    }
    ((float4*)out)[i4] = v;
}

// ---------------- im2col (3x3 stride2 pad1), vectorized x4, fp16 out ----------------
__global__ void im2col_h(const float* __restrict__ x, hf* __restrict__ oh) {
    int idx = blockIdx.x*blockDim.x + threadIdx.x;
    const int total = NTOK*576;
    if (idx >= total) return;
    int c4 = idx % 576; int row = idx / 576;
    int b = row / NPOS; int p = row % NPOS;
    int i = p / WO, j = p % WO;
    int kk = c4 >> 6; int ic = (c4 & 63) * 4;
    int kh = kk / 3, kw = kk % 3;
    int hi = 2*i - 1 + kh, wi = 2*j - 1 + kw;
    float4 v = make_float4(0.f, 0.f, 0.f, 0.f);
    if (hi >= 0 && hi < HI && wi >= 0 && wi < WI)
        v = *(const float4*)(x + ((size_t)(b*(HI*WI) + hi*WI + wi))*DD + ic);
    __half2 h0, h1;
    h0.x = __float2half(v.x); h0.y = __float2half(v.y);
    h1.x = __float2half(v.z); h1.y = __float2half(v.w);
    size_t o = (size_t)row*2304 + kk*256 + ic;
    *(__half2*)(oh + o)     = h0;
    *(__half2*)(oh + o + 2) = h1;
}

__global__ void wseed_tr_hl(const float* __restrict__ w, hf* __restrict__ oh, hf* __restrict__ ol) {
    int idx = blockIdx.x*blockDim.x + threadIdx.x;
    if (idx >= DD*2304) return;
    int oc = idx / 2304; int c = idx % 2304;
    int kk = c >> 8; int ic = c & 255;
    float v = w[(size_t)oc*2304 + ic*9 + kk];
    split_hl(v, oh[idx], ol[idx]);
}

// ---------------- group NA (K=3): 4 groups merged, q read from split-K partials ----------------
__global__ void na3_attn4(const float* __restrict__ kg, const float* __restrict__ qsplit,
                          const float* __restrict__ rpb, const float* __restrict__ tau,
                          float* __restrict__ attn) {
    int blk = blockIdx.x;
    int p = blk % NPOS, b = blk / NPOS;
    int i = p / WO, j = p % WO;
    int t = threadIdx.x; int w = t >> 5; int lane = t & 31;
    __shared__ float kgs[4][256];
    __shared__ float logit[4][9];
    __shared__ float ev[4][9];
    if (t < 128) {
        int n = t >> 6, f = t & 63;
        ((float4*)kgs[n])[f]   = *(const float4*)(kg + ((size_t)(b*4+n)*NPOS + p)*DD + f*4);
        ((float4*)kgs[n+2])[f] = *(const float4*)(kg + ((size_t)(b*4+n+2)*NPOS + p)*DD + f*4);
    }
    int a = w / 3, c = w % 3;
    int si = min(max(i-1,0),25), sj = min(max(j-1,0),25);
    int np = (si+a)*WO + (sj+c);
    const float* q0 = qsplit + (size_t)(b*NPOS + np)*DD;
    const float* q1 = q0 + (size_t)NTOKP*DD;
    float qr[8];
    #pragma unroll
    for (int u=0;u<8;u++) qr[u] = q0[lane + 32*u] + q1[lane + 32*u];
    __syncthreads();
    #pragma unroll
    for (int n = 0; n < 4; n++) {
        float s = 0.f;
        #pragma unroll
        for (int u=0;u<8;u++) s = fmaf(qr[u], kgs[n][lane + 32*u], s);
        #pragma unroll
        for (int o=16;o;o>>=1) s += __shfl_xor_sync(0xffffffffu, s, o);
        if (lane==0) logit[n][w] = s + rpb[n*9 + w];
    }
    __syncthreads();
    if (t < 36) {
        int n = t/9, ac = t%9;
        float scale = expf(tau[0]);
        float m = -1e30f;
        #pragma unroll
        for (int u=0;u<9;u++) m = fmaxf(m, logit[n][u]*scale);
        ev[n][ac] = expf(logit[n][ac]*scale - m);
    }
    __syncthreads();
    if (t < 36) {
        int n = t/9, ac = t%9;
        float sum = 0.f;
        #pragma unroll
        for (int u=0;u<9;u++) sum += ev[n][u];
        attn[((size_t)(b*4+n)*NPOS + p)*9 + ac] = ev[n][ac]/sum + 1e-6f;
    }
}

// ---------------- deterministic column scatter-sum ----------------
__device__ __forceinline__ int inv_list(int s, int* lst) {
    if (s == 0)       { lst[0]=0;  lst[1]=1;  return 2; }
    else if (s == 25) { lst[0]=26; lst[1]=27; return 2; }
    else              { lst[0]=s+1;           return 1; }
}

__global__ void col_sum_k(const float* __restrict__ attn, float* __restrict__ col) {
    int idx = blockIdx.x*blockDim.x + threadIdx.x;
    if (idx >= BB*NPOS) return;
    int t = idx % NPOS, b = idx / NPOS;
    int ti = t / WO, tj = t % WO;
    float acc = 0.f;
    for (int a=0;a<3;a++) {
        int sr = ti - a; if (sr < 0 || sr > 25) continue;
        int il[2]; int ic = inv_list(sr, il);
        for (int c=0;c<3;c++) {
            int sc = tj - c; if (sc < 0 || sc > 25) continue;
            int jl[2]; int jc = inv_list(sc, jl);
            for (int ii=0; ii<ic; ii++)
                for (int jj=0; jj<jc; jj++) {
                    int pp = il[ii]*WO + jl[jj];
                    #pragma unroll
                    for (int n=0;n<4;n++)
                        acc += attn[((size_t)(b*4+n)*NPOS + pp)*9 + a*3 + c];
                }
        }
    }
    col[idx] = acc;
}

// ---------------- group NA AV + in-place residual + fp16 out ----------------
__global__ void na3_av(const float* __restrict__ attn, const float* __restrict__ col,
                       const float* __restrict__ vg, float* __restrict__ xout,
                       hf* __restrict__ oh) {
    int blk = blockIdx.x;
    int p = blk % NPOS, b = blk / NPOS;
    int i = p / WO, j = p % WO;
    int t = threadIdx.x;
    __shared__ float wgt[4][9];
    __shared__ int npos[9];
    if (t < 9) {
        int a = t/3, c = t%3;
        int ni = min(max(i-1,0),25)+a, nj = min(max(j-1,0),25)+c;
        npos[t] = ni*WO + nj;
    }
    __syncthreads();
    if (t < 36) {
        int n = t/9, ac = t%9;
        float av = attn[((size_t)(b*4+n)*NPOS + p)*9 + ac];
        wgt[n][ac] = av / (col[b*NPOS + npos[ac]] + 1e-8f);
    }
    __syncthreads();
    float acc = xout[(size_t)blk*DD + t];
    #pragma unroll
    for (int n=0;n<4;n++) {
        const float* vb = vg + (size_t)(b*4+n)*NPOS*DD;
        #pragma unroll
        for (int ac=0;ac<9;ac++)
            acc = fmaf(wgt[n][ac], vb[(size_t)npos[ac]*DD + t], acc);
    }
    xout[(size_t)blk*DD + t] = acc;
    oh[(size_t)blk*DD + t] = __float2half(acc);
}

// ---------------- RoPE table ----------------
__global__ void rope_tab(float* __restrict__ cs, float* __restrict__ sn) {
    int idx = blockIdx.x*blockDim.x + threadIdx.x;
    if (idx >= NPOS*16) return;
    int pos = idx / 16, r = idx % 16;
    float f = expf(-((float)(2*r) / 32.f) * 9.210340371976184f);
    float ang = (float)pos * f;
    cs[idx] = cosf(ang);
    sn[idx] = sinf(ang);
}

// ---------------- block NA (K=7): row-blocked, smem-staged k/v window ----------------
#define NA7_SMEM ((2*6272 + 8*64) * 4)
__global__ void __launch_bounds__(256)
na7_row(const float* __restrict__ qkv, hf* __restrict__ oh) {
    extern __shared__ float sm7[];
    float* ks = sm7;
    float* vs = sm7 + 6272;
    float* wb = sm7 + 12544;
    int blk = blockIdx.x;
    int i = blk % 28; int bh = blk / 28; int h = bh & 7; int b = bh >> 3;
    int t = threadIdx.x, w = t >> 5, lane = t & 31;
    int si = min(max(i-3,0),21);
    for (int idx = t; idx < 1568; idx += 256) {
        int pos = idx >> 3, f = (idx & 7) * 4;
        int a = pos / 28, c = pos % 28;
        size_t g = ((size_t)(b*NPOS + (si+a)*WO + c))*768 + h*32 + f;
        *(float4*)(ks + pos*32 + f) = *(const float4*)(qkv + g + 256);
        *(float4*)(vs + pos*32 + f) = *(const float4*)(qkv + g + 512);
    }
    __syncthreads();
    for (int j = w; j < 28; j += 8) {
        int sj = min(max(j-3,0),21);
        int p = i*WO + j;
        float qd = qkv[((size_t)(b*NPOS + p))*768 + h*32 + lane];
        for (int nb = 0; nb < 49; nb++) {
            int a = nb / 7, c = nb % 7;
            float s = qd * ks[(a*28 + sj + c)*32 + lane];
            #pragma unroll
            for (int o=16;o;o>>=1) s += __shfl_xor_sync(0xffffffffu, s, o);
            if (lane == 0) wb[w*64 + nb] = s * 0.17677669529663687f;
        }
        __syncwarp();
        float m = -1e30f;
        for (int nb = lane; nb < 49; nb += 32) m = fmaxf(m, wb[w*64 + nb]);
        #pragma unroll
        for (int o=16;o;o>>=1) m = fmaxf(m, __shfl_xor_sync(0xffffffffu, m, o));
        float sum = 0.f;
        for (int nb = lane; nb < 49; nb += 32) {
            float e = expf(wb[w*64 + nb] - m);
            wb[w*64 + nb] = e;
            sum += e;
        }
        #pragma unroll
        for (int o=16;o;o>>=1) sum += __shfl_xor_sync(0xffffffffu, sum, o);
        __syncwarp();
        float inv = 1.f / sum;
        float acc = 0.f;
        for (int nb = 0; nb < 49; nb++) {
            int a = nb / 7, c = nb % 7;
            acc = fmaf(wb[w*64 + nb] * inv, vs[(a*28 + sj + c)*32 + lane], acc);
        }
        size_t o = ((size_t)(b*NPOS + p))*DD + h*32 + lane;
        oh[o] = __float2half(acc);
        __syncwarp();
    }
}

// ---------------- host helpers ----------------
static inline void run_tc64(const hf* Ah, const hf* Bh, const hf* Bl,
                            const float* bias, float* C, hf* Oh,
                            const float* cs, const float* sn,
                            int Mreal, int Mpad, int N, int K, int act, int remap, int ks) {
    dim3 grid(N/64, Mpad/64, ks);
    gemm_mma<64><<<grid, 256, GTC_SMEM64>>>(Ah, Bh, Bl, bias, C, Oh, cs, sn,
                                            Mreal, Mpad, N, K, act, remap, ks);
}
static inline void run_tc128(const hf* Ah, const hf* Bh, const hf* Bl,
                             const float* bias, float* C, hf* Oh,
                             int Mreal, int Mpad, int N, int K, int act, int remap, int ks) {
    dim3 grid(N/64, Mpad/128, ks);
    gemm_mma<128><<<grid, 256, GTC_SMEM128>>>(Ah, Bh, Bl, bias, C, Oh, nullptr, nullptr,
                                              Mreal, Mpad, N, K, act, remap, ks);
}

extern "C" void kernel_launch(void* const* d_in, const int* in_sizes, int n_in,
                              void* d_out, int out_size) {
    const float* x          = (const float*)d_in[0];
    const float* g_seed_w   = (const float*)d_in[1];
    const float* g_q_w      = (const float*)d_in[2];
    const float* g_k_w      = (const float*)d_in[3];
    const float* g_v_w      = (const float*)d_in[4];
    const float* g_mlp_w1   = (const float*)d_in[5];
    const float* g_mlp_b1   = (const float*)d_in[6];
    const float* g_mlp_w2   = (const float*)d_in[7];
    const float* g_mlp_b2   = (const float*)d_in[8];
    const float* g_ln_in_g  = (const float*)d_in[9];
    const float* g_ln_in_b  = (const float*)d_in[10];
    const float* g_ln_out_g = (const float*)d_in[11];
    const float* g_ln_out_b = (const float*)d_in[12];
    const float* g_tau      = (const float*)d_in[13];
    const float* g_rpb      = (const float*)d_in[14];
    const float* blk_ln1_g  = (const float*)d_in[15];
    const float* blk_ln1_b  = (const float*)d_in[16];
    const float* blk_qkv_w  = (const float*)d_in[17];
    const float* blk_proj_w = (const float*)d_in[18];
    const float* blk_proj_b = (const float*)d_in[19];
    const float* blk_ln2_g  = (const float*)d_in[20];
    const float* blk_ln2_b  = (const float*)d_in[21];
    const float* blk_mlp_w1 = (const float*)d_in[22];
    const float* blk_mlp_b1 = (const float*)d_in[23];
    const float* blk_mlp_w2 = (const float*)d_in[24];
    const float* blk_mlp_b2 = (const float*)d_in[25];
    float* out = (float*)d_out;

    cudaFuncSetAttribute(gemm_mma<64>,  cudaFuncAttributeMaxDynamicSharedMemorySize, GTC_SMEM64);
    cudaFuncSetAttribute(gemm_mma<128>, cudaFuncAttributeMaxDynamicSharedMemorySize, GTC_SMEM128);
    cudaFuncSetAttribute(na7_row, cudaFuncAttributeMaxDynamicSharedMemorySize, NA7_SMEM);

#define SYM(v, s) cudaGetSymbolAddress((void**)&v, s)
    float *xout, *buf2, *kg, *vg, *split, *attn, *colsum, *csb, *snb;
    SYM(xout,g_xout); SYM(buf2,g_buf2);
    SYM(kg,g_kg); SYM(vg,g_vg); SYM(split,g_split); SYM(attn,g_attn);
    SYM(colsum,g_colsum); SYM(csb,g_cos); SYM(snb,g_sin);
    hf *xh,*lnxh,*colh,*a1h,*a2h;
    SYM(xh,g_xh); SYM(lnxh,g_lnxh); SYM(colh,g_colh);
    SYM(a1h,g_a1h); SYM(a2h,g_a2h);
    hf *wsh,*wsl,*wqh,*wql,*wkh,*wkl,*wvh,*wvl,*m1h,*m1l,*m2h,*m2l;
    SYM(wsh,g_wsh); SYM(wsl,g_wsl); SYM(wqh,g_wqh); SYM(wql,g_wql);
    SYM(wkh,g_wkh); SYM(wkl,g_wkl); SYM(wvh,g_wvh); SYM(wvl,g_wvl);
    SYM(m1h,g_m1h); SYM(m1l,g_m1l); SYM(m2h,g_m2h); SYM(m2l,g_m2l);
    hf *qkvh,*qkvl,*pjh,*pjl,*bm1h,*bm1l,*bm2h,*bm2l;
    SYM(qkvh,g_qkvh); SYM(qkvl,g_qkvl); SYM(pjh,g_pjh); SYM(pjl,g_pjl);
    SYM(bm1h,g_bm1h); SYM(bm1l,g_bm1l); SYM(bm2h,g_bm2h); SYM(bm2l,g_bm2l);
#undef SYM

    // ---- weight conversions ----
    wseed_tr_hl<<<(DD*2304 + 255)/256, 256>>>(g_seed_w, wsh, wsl);
    {
        CvtSegs cs;
        cs.src[0]=g_q_w;      cs.hi[0]=wqh;  cs.lo[0]=wql;
        cs.src[1]=g_k_w;      cs.hi[1]=wkh;  cs.lo[1]=wkl;
        cs.src[2]=g_v_w;      cs.hi[2]=wvh;  cs.lo[2]=wvl;
        cs.src[3]=g_mlp_w1;   cs.hi[3]=m1h;  cs.lo[3]=m1l;
        cs.src[4]=g_mlp_w2;   cs.hi[4]=m2h;  cs.lo[4]=m2l;
        cs.src[5]=blk_qkv_w;  cs.hi[5]=qkvh; cs.lo[5]=qkvl;
        cs.src[6]=blk_proj_w; cs.hi[6]=pjh;  cs.lo[6]=pjl;
        cs.src[7]=blk_mlp_w1; cs.hi[7]=bm1h; cs.lo[7]=bm1l;
        cs.src[8]=blk_mlp_w2; cs.hi[8]=bm2h; cs.lo[8]=bm2l;
        cvt_all<<<(CVT_TOT + 255)/256, 256>>>(cs);
    }

    // ---- LN_in(x) + raw x fp16 in one pass ----
    ln_warp<<<(NTOKIN + 7)/8, 256>>>(x, g_ln_in_g, g_ln_in_b, lnxh, xh, NTOKIN);
    run_tc128(lnxh, wkh, wkl, nullptr, kg, nullptr, NTOKIN, NTOKIN, DD, DD, 0, 1, 1);
    run_tc128(xh,   wvh, wvl, nullptr, vg, nullptr, NTOKIN, NTOKIN, DD, DD, 0, 1, 1);

    // ---- seed conv ----
    im2col_h<<<(NTOK*576 + 255)/256, 256>>>(x, colh);
    run_tc128(colh, wsh, wsl, nullptr, split, nullptr, NTOK, NTOKP, DD, 2304, 0, 0, 3);
    combine_ln2<<<(NTOK + 7)/8, 256>>>(split, 3, nullptr, g_ln_out_g, g_ln_out_b,
                                       nullptr, xout, g_ln_out_g, g_ln_out_b,
                                       a2h, NTOKP, NTOK);

    rope_tab<<<(NPOS*16 + 255)/256, 256>>>(csb, snb);

    // ---- 3 grouped-NA seeding iterations ----
    for (int it = 0; it < 3; it++) {
        run_tc64(a2h, wqh, wql, nullptr, split, nullptr, nullptr, nullptr,
                 NTOK, NTOKP, DD, DD, 0, 0, 2);
        na3_attn4<<<NTOK, 288>>>(kg, split, g_rpb, g_tau, attn);
        col_sum_k<<<(BB*NPOS + 255)/256, 256>>>(attn, colsum);
        na3_av<<<NTOK, 256>>>(attn, colsum, vg, xout, a2h);
        run_tc64(a2h, m1h, m1l, g_mlp_b1, nullptr, a1h, nullptr, nullptr,
                 NTOK, NTOKP, 512, DD, 1, 0, 1);
        run_tc64(a1h, m2h, m2l, nullptr, split, nullptr, nullptr, nullptr,
                 NTOK, NTOKP, DD, 512, 0, 0, 2);
        const float* g2 = (it < 2) ? g_ln_out_g : blk_ln1_g;
        const float* b2 = (it < 2) ? g_ln_out_b : blk_ln1_b;
        combine_ln2<<<(NTOK + 7)/8, 256>>>(split, 2, g_mlp_b2, g_ln_out_g, g_ln_out_b,
                                           xout, xout, g2, b2, a2h, NTOKP, NTOK);
    }

    // ---- 2 transformer blocks with 7x7 NA ----
    for (int l = 0; l < 2; l++) {
        run_tc64(a2h, qkvh + (size_t)l*768*DD, qkvl + (size_t)l*768*DD,
                 nullptr, buf2, nullptr, csb, snb,
                 NTOK, NTOKP, 768, DD, 0, 0, 1);
        na7_row<<<BB*HEADS*28, 256, NA7_SMEM>>>(buf2, a2h);
        run_tc64(a2h, pjh + (size_t)l*DD*DD, pjl + (size_t)l*DD*DD,
                 nullptr, split, nullptr, nullptr, nullptr,
                 NTOK, NTOKP, DD, DD, 0, 0, 2);
        combine_res_ln<<<(NTOK + 7)/8, 256>>>(split, 2, blk_proj_b + l*DD, xout, xout,
                                              blk_ln2_g + l*DD, blk_ln2_b + l*DD,
                                              a2h, NTOKP, NTOK);
        run_tc64(a2h, bm1h + (size_t)l*768*DD, bm1l + (size_t)l*768*DD,
                 blk_mlp_b1 + l*768, nullptr, a1h, nullptr, nullptr,
                 NTOK, NTOKP, 768, DD, 1, 0, 1);
        run_tc64(a1h, bm2h + (size_t)l*DD*768, bm2l + (size_t)l*DD*768,
                 nullptr, split, nullptr, nullptr, nullptr,
                 NTOK, NTOKP, DD, 768, 0, 0, 2);
        if (l == 0) {
            combine_res_ln<<<(NTOK + 7)/8, 256>>>(split, 2, blk_mlp_b2, xout, xout,
                                                  blk_ln1_g + DD, blk_ln1_b + DD,
                                                  a2h, NTOKP, NTOK);
        } else {
            int tot4 = (NTOK*DD) >> 2;
            combine_k<<<(tot4 + 255)/256, 256>>>(split, 2, blk_mlp_b2 + DD, xout, out,
                                                 NTOK, NTOKP, DD, 0);
        }
    }
}